// round 10
// baseline (speedup 1.0000x reference)
#include <cuda_runtime.h>
#include <cuda_bf16.h>
#include <math.h>
#include <stdint.h>

#define NB    8
#define NEq   256
#define SSq   21
#define NSTEP 20
#define DDim  256
#define HHn   8
#define HDn   32
#define VVn   10000
#define TTn   1920
#define VPAD  10112
#define MTOT  (NSTEP*NEq)   // 5120
#define LOOPBLK 256
#define BST   12
#define SMEMSZ  (33792 + 2*128*BST*4)   // 46080 (GEMM scratch)
#define CTXOFF  46080
#define AWOFF   (CTXOFF + 17408)        // 63488
#define SMEMLOOP (AWOFF + 1024)         // 64512
#define SMEMS2  (2*128*12*4*2)          // 24576

// ------------------------- device scratch -------------------------
__device__ __align__(16) float g_value [NB*HHn*TTn*HDn];
__device__ __align__(16) float g_U     [NEq*1536];   // h@[offaw_top|hsw|whh_gi]
__device__ __align__(16) float g_ae    [NEq*512];    // [attn | emb]
__device__ __align__(16) float g_qgpc  [NEq*1280];   // [query@wih_q_gi (1024) | query@offaw_bot (256)]
__device__ __align__(16) float g_h     [NEq*DDim];
__device__ __align__(16) float g_c     [NEq*DDim];
__device__ __align__(16) float g_hsbc  [256];
__device__ __align__(16) float g_lss   [MTOT*80];
__device__ __align__(16) float g_lse   [MTOT];
__device__ __align__(16) __nv_bfloat16 g_hseqb  [MTOT*DDim];
__device__ __align__(16) __nv_bfloat16 g_bigw2t [1536*256];   // [n][k]
__device__ __align__(16) __nv_bfloat16 g_w21t   [1024*512];   // [n][k], k: attn(256)|emb(256)
__device__ __align__(16) __nv_bfloat16 g_wct    [1280*256];   // const-gemm weights
__device__ __align__(16) __nv_bfloat16 g_logitwt[VPAD*256];
__device__ __align__(16) __nv_bfloat16 g_ctxwt  [256*32];
__device__ __align__(16) __nv_bfloat16 g_valuewt[256*256];

__device__ unsigned g_bar_cnt;
__device__ volatile unsigned g_bar_gen;

// ------------------------- helpers -------------------------
__device__ __forceinline__ float tanha(float x) {
    float y; asm("tanh.approx.f32 %0, %1;" : "=f"(y) : "f"(x)); return y;
}
__device__ __forceinline__ void mma16816(float* c, const uint32_t* a, const uint32_t* b) {
    asm volatile(
        "mma.sync.aligned.m16n8k16.row.col.f32.bf16.bf16.f32 "
        "{%0,%1,%2,%3}, {%4,%5,%6,%7}, {%8,%9}, {%0,%1,%2,%3};"
        : "+f"(c[0]), "+f"(c[1]), "+f"(c[2]), "+f"(c[3])
        : "r"(a[0]), "r"(a[1]), "r"(a[2]), "r"(a[3]), "r"(b[0]), "r"(b[1]));
}
__device__ __forceinline__ void cpasync16(uint32_t dst, const void* src) {
    asm volatile("cp.async.cg.shared.global [%0], [%1], 16;" :: "r"(dst), "l"(src));
}

// flat single-counter grid barrier (measured best in R8)
__device__ __forceinline__ void gridbar() {
    __syncthreads();
    if (threadIdx.x == 0) {
        __threadfence();
        unsigned gen = g_bar_gen;
        if (atomicAdd(&g_bar_cnt, 1u) == (unsigned)(LOOPBLK - 1)) {
            g_bar_cnt = 0;
            __threadfence();
            g_bar_gen = gen + 1u;
        } else {
            while (g_bar_gen == gen) { }
            __threadfence();
        }
    }
    __syncthreads();
}

// ------------------------- GEMM mainloop (64x128 tile, 8 warps, K multi-chunk) ----------
template<int KCHUNK>
__device__ __forceinline__ void gemm_core(
    const float* __restrict__ A, int lda,
    const __nv_bfloat16* __restrict__ Wt, int ldw,
    int n0, int row0, int kbeg, char* smem, float acc[2][4][4])
{
    uint32_t* Asw = (uint32_t*)smem;                 // [64][132] words (256-k chunk)
    uint32_t* Bsw = (uint32_t*)(smem + 33792);       // [2][128][BST] words
    const int SAW = 132;
    const int NKT = KCHUNK >> 4;
    constexpr int KC = (KCHUNK < 256) ? KCHUNK : 256;

    const int tid  = threadIdx.x;
    const int lane = tid & 31, warp = tid >> 5;
    const int wm = warp >> 2, wn = warp & 3;
    const int g = lane >> 2, t = lane & 3;
    const int bn = tid >> 1, bq = (tid & 1) << 3;
    const uint32_t bsm = (uint32_t)__cvta_generic_to_shared(Bsw);

    cpasync16(bsm + (uint32_t)((bn*BST + (bq>>1))*4),
              Wt + (size_t)(n0 + bn) * ldw + kbeg + bq);
    asm volatile("cp.async.commit_group;");

#pragma unroll
    for (int i = 0; i < 2; i++)
#pragma unroll
        for (int j = 0; j < 4; j++)
#pragma unroll
            for (int q = 0; q < 4; q++) acc[i][j][q] = 0.f;

#pragma unroll 1
    for (int ksg = 0; ksg < NKT; ksg++) {
        __syncthreads();
        if ((ksg & 15) == 0) {
            int kA = kbeg + ((ksg >> 4) << 8);
#pragma unroll
            for (int idx = tid * 4; idx < 64 * KC; idx += 1024) {
                int r = idx / KC, cc = idx % KC;
                float4 v = *(const float4*)(A + (size_t)(row0 + r) * lda + kA + cc);
                __nv_bfloat162 p0 = __float22bfloat162_rn(make_float2(v.x, v.y));
                __nv_bfloat162 p1 = __float22bfloat162_rn(make_float2(v.z, v.w));
                Asw[r * SAW + (cc >> 1)]     = *(uint32_t*)&p0;
                Asw[r * SAW + (cc >> 1) + 1] = *(uint32_t*)&p1;
            }
        }
        if (ksg + 1 < NKT)
            cpasync16(bsm + (uint32_t)(((((ksg+1)&1)*128*BST) + bn*BST + (bq>>1))*4),
                      Wt + (size_t)(n0 + bn) * ldw + kbeg + (ksg + 1) * 16 + bq);
        asm volatile("cp.async.commit_group;");
        asm volatile("cp.async.wait_group 1;");
        __syncthreads();

        const int wo = (ksg & 15) * 8;
        uint32_t a[2][4];
#pragma unroll
        for (int mt = 0; mt < 2; mt++) {
            const uint32_t* ap = Asw + (wm*32 + mt*16 + g) * SAW + wo + t;
            a[mt][0] = ap[0];
            a[mt][1] = ap[8 * SAW];
            a[mt][2] = ap[4];
            a[mt][3] = ap[8 * SAW + 4];
        }
        const uint32_t* bbase = Bsw + (ksg & 1) * 128 * BST;
        uint32_t bf[4][2];
#pragma unroll
        for (int nt = 0; nt < 4; nt++) {
            const uint32_t* bp = bbase + (wn*32 + nt*8 + g) * BST + t;
            bf[nt][0] = bp[0];
            bf[nt][1] = bp[4];
        }
#pragma unroll
        for (int mt = 0; mt < 2; mt++)
#pragma unroll
            for (int nt = 0; nt < 4; nt++)
                mma16816(acc[mt][nt], a[mt], bf[nt]);
    }
}

__device__ __forceinline__ void epi_partials(float acc[2][4][4], float* C, int N,
                                             int n0, int row0)
{
    const int lane = threadIdx.x & 31, warp = threadIdx.x >> 5;
    const int wm = warp >> 2, wn = warp & 3;
    const int g = lane >> 2, t = lane & 3;
#pragma unroll
    for (int mt = 0; mt < 2; mt++) {
        int m = row0 + wm*32 + mt*16 + g;
#pragma unroll
        for (int nt = 0; nt < 4; nt++) {
            int n = n0 + wn*32 + nt*8 + (t << 1);
            float* c = acc[mt][nt];
            *(float2*)(C + (size_t)m * N + n)       = make_float2(c[0], c[1]);
            *(float2*)(C + (size_t)(m + 8) * N + n) = make_float2(c[2], c[3]);
        }
    }
}

// ------------------------- fused preamble GEMMs: value + const (query@wct) -------------
__global__ __launch_bounds__(256, 2)
void gemms_pre(const float* __restrict__ enc, const float* __restrict__ valueb,
               const float* __restrict__ mask, const float* __restrict__ query)
{
    extern __shared__ char smem[];
    float acc[2][4][4];
    const int blk = blockIdx.x;
    if (blk < 480) {
        const int bx = blk & 1, by = blk >> 1;
        const int n0 = bx*128, row0 = by*64;
        gemm_core<256>(enc, 256, g_valuewt, 256, n0, row0, 0, smem, acc);
        const int lane = threadIdx.x & 31, warp = threadIdx.x >> 5;
        const int wm = warp >> 2, wn = warp & 3;
        const int g = lane >> 2, t = lane & 3;
#pragma unroll
        for (int mt = 0; mt < 2; mt++) {
#pragma unroll
            for (int mi = 0; mi < 2; mi++) {
                int m  = row0 + wm*32 + mt*16 + g + mi*8;
                int b  = m / TTn;
                int tt = m - b * TTn;
                float mk = mask[m];
#pragma unroll
                for (int nt = 0; nt < 4; nt++) {
                    int n = n0 + wn*32 + nt*8 + (t << 1);
                    int h = n >> 5, hd = n & 31;
                    float* c = acc[mt][nt];
                    float v0 = (c[mi*2]   + valueb[n])     * mk;
                    float v1 = (c[mi*2+1] + valueb[n + 1]) * mk;
                    *(float2*)(g_value + (((size_t)(b*HHn + h))*TTn + tt)*HDn + hd)
                        = make_float2(v0, v1);
                }
            }
        }
    } else {
        const int cb = blk - 480;                // 40 blocks: qgpc = query @ wct
        const int bx = cb % 10, by = cb / 10;
        gemm_core<256>(query, 256, g_wct, 256, bx*128, by*64, 0, smem, acc);
        epi_partials(acc, g_qgpc, 1280, bx*128, by*64);
    }
}

// ------------------------- streaming 128x128 GEMM core (logits) -------------------------
__device__ __forceinline__ void stream_core(const __nv_bfloat16* __restrict__ Ag0,
                                            const __nv_bfloat16* __restrict__ Bg0,
                                            char* smem, float acc[4][4][4])
{
    uint32_t* As = (uint32_t*)smem;
    uint32_t* Bs = (uint32_t*)(smem + 12288);
    const int tid = threadIdx.x;
    const int lane = tid & 31, warp = tid >> 5;
    const int wm = warp >> 2, wn = warp & 3;
    const int g = lane >> 2, t = lane & 3;
    const int lr = tid >> 1, lc = (tid & 1) << 3;
    const uint32_t asmb = (uint32_t)__cvta_generic_to_shared(As);
    const uint32_t bsmb = (uint32_t)__cvta_generic_to_shared(Bs);
    const uint32_t loff = (uint32_t)((lr*12 + (lc>>1))*4);
    const __nv_bfloat16* Ag = Ag0 + (size_t)lr*256 + lc;
    const __nv_bfloat16* Bg = Bg0 + (size_t)lr*256 + lc;

    cpasync16(asmb + loff, Ag);
    cpasync16(bsmb + loff, Bg);
    asm volatile("cp.async.commit_group;");

#pragma unroll
    for (int i = 0; i < 4; i++)
#pragma unroll
        for (int j = 0; j < 4; j++)
#pragma unroll
            for (int q = 0; q < 4; q++) acc[i][j][q] = 0.f;

#pragma unroll 1
    for (int ks = 0; ks < 16; ks++) {
        __syncthreads();
        if (ks + 1 < 16) {
            uint32_t bo = (uint32_t)(((ks + 1) & 1) * 6144);
            cpasync16(asmb + bo + loff, Ag + (ks + 1) * 16);
            cpasync16(bsmb + bo + loff, Bg + (ks + 1) * 16);
        }
        asm volatile("cp.async.commit_group;");
        asm volatile("cp.async.wait_group 1;");
        __syncthreads();

        const uint32_t* Ab = As + (ks & 1) * 1536;
        const uint32_t* Bb = Bs + (ks & 1) * 1536;
        uint32_t a[4][4];
#pragma unroll
        for (int mt = 0; mt < 4; mt++) {
            const uint32_t* ap = Ab + (wm*64 + mt*16 + g) * 12 + t;
            a[mt][0] = ap[0];
            a[mt][1] = ap[8 * 12];
            a[mt][2] = ap[4];
            a[mt][3] = ap[8 * 12 + 4];
        }
        uint32_t b[4][2];
#pragma unroll
        for (int nt = 0; nt < 4; nt++) {
            const uint32_t* bp = Bb + (wn*32 + nt*8 + g) * 12 + t;
            b[nt][0] = bp[0];
            b[nt][1] = bp[4];
        }
#pragma unroll
        for (int mt = 0; mt < 4; mt++)
#pragma unroll
            for (int nt = 0; nt < 4; nt++)
                mma16816(acc[mt][nt], a[mt], b[nt]);
    }
}

__global__ __launch_bounds__(256, 2)
void logits_stream1(const float* __restrict__ logitb)
{
    extern __shared__ char smem[];
    float acc[4][4][4];
    const int n0 = blockIdx.x * 128, row0 = blockIdx.y * 128;
    stream_core(g_hseqb + (size_t)row0*256, g_logitwt + (size_t)n0*256, smem, acc);

    const int tid = threadIdx.x;
    const int lane = tid & 31, warp = tid >> 5;
    const int wm = warp >> 2, wn = warp & 3;
    const int g = lane >> 2, t = lane & 3;

    float bias_r[4][2];
#pragma unroll
    for (int nt = 0; nt < 4; nt++) {
        int n = n0 + wn*32 + nt*8 + (t << 1);
        bias_r[nt][0] = (n     < VVn) ? logitb[n]     : 0.f;
        bias_r[nt][1] = (n + 1 < VVn) ? logitb[n + 1] : 0.f;
    }

    __syncthreads();
    float* s_ps = (float*)smem;
#pragma unroll
    for (int mt = 0; mt < 4; mt++) {
#pragma unroll
        for (int mi = 0; mi < 2; mi++) {
            int mloc = wm*64 + mt*16 + g + mi*8;
            float ls = 0.f;
#pragma unroll
            for (int nt = 0; nt < 4; nt++) {
                int n = n0 + wn*32 + nt*8 + (t << 1);
#pragma unroll
                for (int e = 0; e < 2; e++)
                    if (n + e < VVn)
                        ls += __expf(acc[mt][nt][mi*2 + e] + bias_r[nt][e]);
            }
            ls += __shfl_xor_sync(0xffffffffu, ls, 1);
            ls += __shfl_xor_sync(0xffffffffu, ls, 2);
            if (t == 0) s_ps[mloc*4 + wn] = ls;
        }
    }
    __syncthreads();
    if (tid < 128) {
        float ls = s_ps[tid*4] + s_ps[tid*4+1] + s_ps[tid*4+2] + s_ps[tid*4+3];
        g_lss[(size_t)(row0 + tid)*80 + blockIdx.x] = ls;
    }
}

__global__ __launch_bounds__(256)
void lse_reduce()
{
    const int w = threadIdx.x >> 5, lane = threadIdx.x & 31;
    const int m = blockIdx.x * 8 + w;
    float s = 0.f;
    const float* p = g_lss + (size_t)m * 80;
    if (lane < 79)       s  = p[lane];
    if (lane + 32 < 79)  s += p[lane + 32];
    if (lane + 64 < 79)  s += p[lane + 64];
#pragma unroll
    for (int o = 16; o; o >>= 1) s += __shfl_xor_sync(0xffffffffu, s, o);
    if (lane == 0) g_lse[m] = logf(s);
}

__global__ __launch_bounds__(256, 2)
void logits_stream2(const float* __restrict__ logitb, float* __restrict__ out)
{
    extern __shared__ char smem[];
    float acc[4][4][4];
    const int n0 = blockIdx.x * 128, row0 = blockIdx.y * 128;
    stream_core(g_hseqb + (size_t)row0*256, g_logitwt + (size_t)n0*256, smem, acc);

    const int lane = threadIdx.x & 31, warp = threadIdx.x >> 5;
    const int wm = warp >> 2, wn = warp & 3;
    const int g = lane >> 2, t = lane & 3;

#pragma unroll
    for (int mt = 0; mt < 4; mt++) {
#pragma unroll
        for (int mi = 0; mi < 2; mi++) {
            int m  = row0 + wm*64 + mt*16 + g + mi*8;
            int q  = m & 255, st = m >> 8;
            float lse = g_lse[m];
            float* orow = out + ((size_t)q * NSTEP + st) * VVn;
#pragma unroll
            for (int nt = 0; nt < 4; nt++) {
                int n = n0 + wn*32 + nt*8 + (t << 1);
                if (n < VVn) {
                    float* c = acc[mt][nt];
                    *(float2*)(orow + n) = make_float2(c[mi*2]   + logitb[n]   - lse,
                                                       c[mi*2+1] + logitb[n+1] - lse);
                }
            }
        }
    }
}

// ------------------------- preamble: all weight transposes -------------------------
__global__ __launch_bounds__(256)
void prep_transposes(const float* __restrict__ lw,
                     const float* __restrict__ wih, const float* __restrict__ whh,
                     const float* __restrict__ offw, const float* __restrict__ aww,
                     const float* __restrict__ hsw)
{
    __shared__ float s_t[64][65];
    const int blk = blockIdx.x;
    const int tx = threadIdx.x & 63, ty = threadIdx.x >> 6;

    if (blk < 632) {                                    // logitwt: 158 x 4
        const int n0 = (blk % 158) * 64, k0 = (blk / 158) * 64;
#pragma unroll
        for (int rr = ty; rr < 64; rr += 4)
            s_t[rr][tx] = (n0 + tx < VVn) ? lw[(size_t)(k0 + rr) * VVn + n0 + tx] : 0.f;
        __syncthreads();
#pragma unroll
        for (int rr = ty; rr < 64; rr += 4)
            g_logitwt[(size_t)(n0 + rr) * 256 + k0 + tx] = __float2bfloat16(s_t[tx][rr]);
    } else if (blk < 760) {                             // w21t: 16 n x 8 k tiles
        const int idx = blk - 632;
        const int n0 = (idx & 15) * 64, k0 = (idx >> 4) * 64;
#pragma unroll
        for (int rr = ty; rr < 64; rr += 4) {
            int k = k0 + rr, n = n0 + tx;
            int j = (n & 3) * 256 + (n >> 2);
            s_t[rr][tx] = (k < 256) ? wih[(size_t)(256 + k) * 1024 + j]
                                    : wih[(size_t)(k - 256) * 1024 + j];
        }
        __syncthreads();
#pragma unroll
        for (int rr = ty; rr < 64; rr += 4)
            g_w21t[(size_t)(n0 + rr) * 512 + k0 + tx] = __float2bfloat16(s_t[tx][rr]);
    } else if (blk < 856) {                             // bigw2t: 24 n x 4 k tiles
        const int idx = blk - 760;
        const int n0 = (idx % 24) * 64, k0 = (idx / 24) * 64;
#pragma unroll
        for (int rr = ty; rr < 64; rr += 4) {
            int k = k0 + rr, n = n0 + tx;
            float v;
            if (n < 128)      v = offw[k*128 + n];
            else if (n < 256) v = aww[k*128 + (n - 128)];
            else if (n < 512) v = hsw[k*256 + (n - 256)];
            else {
                int m = n - 512;
                v = whh[(size_t)k * 1024 + (m & 3) * 256 + (m >> 2)];
            }
            s_t[rr][tx] = v;
        }
        __syncthreads();
#pragma unroll
        for (int rr = ty; rr < 64; rr += 4)
            g_bigw2t[(size_t)(n0 + rr) * 256 + k0 + tx] = __float2bfloat16(s_t[tx][rr]);
    } else {                                            // wct: 20 n x 4 k tiles
        const int idx = blk - 856;
        const int n0 = (idx % 20) * 64, k0 = (idx / 20) * 64;
#pragma unroll
        for (int rr = ty; rr < 64; rr += 4) {
            int k = k0 + rr, n = n0 + tx;
            float v;
            if (n < 1024)
                v = wih[(size_t)(512 + k) * 1024 + (n & 3) * 256 + (n >> 2)];
            else {
                int m = n - 1024;
                v = (m < 128) ? offw[(256 + k)*128 + m] : aww[(256 + k)*128 + (m - 128)];
            }
            s_t[rr][tx] = v;
        }
        __syncthreads();
#pragma unroll
        for (int rr = ty; rr < 64; rr += 4)
            g_wct[(size_t)(n0 + rr) * 256 + k0 + tx] = __float2bfloat16(s_t[tx][rr]);
    }
}

__global__ __launch_bounds__(256)
void build_small(const float* __restrict__ ctxw, const float* __restrict__ valuew,
                 const float* __restrict__ hsb,  const float* __restrict__ ctxb)
{
    const int blk = blockIdx.x, tid = threadIdx.x;
    if (blk < 256) {
        int q = blk;
        g_h[q*256 + tid] = 0.f;
        g_c[q*256 + tid] = 0.f;
#pragma unroll
        for (int j = 0; j < 6; j++) g_U[q*1536 + j*256 + tid] = 0.f;
        if (q == 0) g_hsbc[tid] = hsb[tid] + ctxb[tid];
    } else {
        int i = (blk - 256) * 256 + tid;                // 0..65535
        if (i < 256*32) {
            int n = i >> 5, k = i & 31;
            g_ctxwt[n*32 + k] = __float2bfloat16(ctxw[k*256 + n]);
        }
        int n = i >> 8, k = i & 255;
        g_valuewt[n*256 + k] = __float2bfloat16(valuew[k*256 + n]);
    }
}

// ------------------------- fused MSDA (one query per block; persistent ctx) -------------
__device__ void msda_one(int n, int step,
                         const float* __restrict__ rp,   const float* __restrict__ vr,
                         const int*   __restrict__ seq,  const float* __restrict__ embw,
                         const float* __restrict__ offb, const float* __restrict__ awb,
                         const float* __restrict__ alphab, char* smem)
{
    uint32_t* s_hsampb = (uint32_t*)smem;              // [128][17]
    float* s_hb    = (float*)(smem + 8704);
    float* s_off   = (float*)(smem + 9728);
    float* s_aw    = (float*)(smem + 10240);
    float* s_alpha = (float*)(smem + 10752);
    float* s_wgt   = (float*)(smem + 11264);
    const uint32_t* s_ctx = (const uint32_t*)(smem + CTXOFF);
    const float*    s_aww = (const float*)(smem + AWOFF);

    const int b    = n >> 5;
    const int tid  = threadIdx.x;
    const int lane = tid & 31;
    const int w    = tid >> 5;

    __syncthreads();

    {
        int tok = (step == 0) ? 1 : seq[n*SSq + step - 1];
        g_ae[n*512 + 256 + tid] = embw[(size_t)tok * DDim + tid];
        s_hb[tid] = g_U[n*1536 + 256 + tid] + g_hsbc[tid];
    }
    if (tid < 128) {
        float so = g_U[n*1536 + tid]       + g_qgpc[n*1280 + 1024 + tid] + offb[tid];
        float sa = g_U[n*1536 + 128 + tid] + g_qgpc[n*1280 + 1152 + tid] + awb[tid];
        s_off[tid] = so;
        float m = sa;
#pragma unroll
        for (int o = 8; o; o >>= 1) m = fmaxf(m, __shfl_xor_sync(0xffffffffu, m, o));
        float e = __expf(sa - m);
        float sm = e;
#pragma unroll
        for (int o = 8; o; o >>= 1) sm += __shfl_xor_sync(0xffffffffu, sm, o);
        s_aw[tid] = e / sm;
    }
    __syncthreads();

    {
        const float rpn = rp[n];
        __nv_bfloat16* hs = (__nv_bfloat16*)s_hsampb;
#pragma unroll
        for (int i = 0; i < 16; i++) {
            int r = (w << 4) + i;
            int h = r >> 4;
            int l = (r >> 2) & 3;
            int shape_l = 1024 >> l;
            int start_l = 2048 - (2048 >> l);
            float refl = rpn * vr[b*4 + l];
            float x = refl * (float)shape_l + s_off[r] - 0.5f;
            float x0f = floorf(x);
            float wf = x - x0f;
            int x0 = (int)x0f;
            const float* vbase = g_value + (((size_t)(b*HHn + h))*TTn + start_l) * HDn;
            float g0 = (x0 >= 0     && x0     < shape_l) ? vbase[(size_t)x0     * HDn + lane] : 0.f;
            float g1 = (x0 + 1 >= 0 && x0 + 1 < shape_l) ? vbase[(size_t)(x0+1) * HDn + lane] : 0.f;
            hs[r*34 + lane] = __float2bfloat16((g0 * (1.f - wf) + g1 * wf) * s_aw[r]);
        }
    }
    __syncthreads();

    {
        const int g = lane >> 2, t = lane & 3;
        const int r0 = w << 4;
        const float ab = alphab[0];

        uint32_t a[2][4];
#pragma unroll
        for (int ks = 0; ks < 2; ks++) {
            const uint32_t* ap = s_hsampb + (r0 + g) * 17 + ks*8 + t;
            a[ks][0] = ap[0];
            a[ks][1] = ap[8 * 17];
            a[ks][2] = ap[4];
            a[ks][3] = ap[8 * 17 + 4];
        }
        float p0 = 0.f, p1 = 0.f;
#pragma unroll
        for (int nb = 0; nb < 256; nb += 8) {
            float c[4] = {0.f, 0.f, 0.f, 0.f};
#pragma unroll
            for (int ks = 0; ks < 2; ks++) {
                const uint32_t* bp = s_ctx + (nb + g) * 17 + ks*8 + t;
                uint32_t bf2[2] = { bp[0], bp[4] };
                mma16816(c, a[ks], bf2);
            }
            int col = nb + (t << 1);
            float hb0 = s_hb[col], hb1 = s_hb[col + 1];
            float aw0 = s_aww[col], aw1 = s_aww[col + 1];
            p0 = fmaf(tanha(c[0] + hb0), aw0, fmaf(tanha(c[1] + hb1), aw1, p0));
            p1 = fmaf(tanha(c[2] + hb0), aw0, fmaf(tanha(c[3] + hb1), aw1, p1));
        }
        p0 += __shfl_xor_sync(0xffffffffu, p0, 1);
        p0 += __shfl_xor_sync(0xffffffffu, p0, 2);
        p1 += __shfl_xor_sync(0xffffffffu, p1, 1);
        p1 += __shfl_xor_sync(0xffffffffu, p1, 2);
        if (t == 0) {
            s_alpha[r0 + g]     = p0 + ab;
            s_alpha[r0 + g + 8] = p1 + ab;
        }
    }
    __syncthreads();

    if (tid < 128) {
        float v = s_alpha[tid];
        float m = v;
#pragma unroll
        for (int o = 8; o; o >>= 1) m = fmaxf(m, __shfl_xor_sync(0xffffffffu, m, o));
        float e = __expf(v - m);
        float sm = e;
#pragma unroll
        for (int o = 8; o; o >>= 1) sm += __shfl_xor_sync(0xffffffffu, sm, o);
        s_wgt[tid] = e / sm;
    }
    __syncthreads();

    {
        int h = tid >> 5, hd = tid & 31;
        const __nv_bfloat16* hs = (const __nv_bfloat16*)s_hsampb;
        float res = 0.f;
#pragma unroll
        for (int lp = 0; lp < 16; lp++)
            res = fmaf(s_wgt[(h << 4) + lp],
                       __bfloat162float(hs[((h << 4) + lp)*34 + hd]), res);
        g_ae[n*512 + tid] = res;
    }
}

// ------------------------- persistent recurrent loop (3 barriers/step) -------------------
__global__ __launch_bounds__(256, 2)
void loop_kernel(const float* __restrict__ rp,   const float* __restrict__ vr,
                 const int*   __restrict__ seq,  const float* __restrict__ embw,
                 const float* __restrict__ offb, const float* __restrict__ awb,
                 const float* __restrict__ alphaw, const float* __restrict__ alphab)
{
    extern __shared__ char smem[];
    const int blk = blockIdx.x;
    const int tid = threadIdx.x;

    // load persistent ctx + alphaw once
    {
        uint32_t* s_ctx = (uint32_t*)(smem + CTXOFF);
        const uint32_t* cg = (const uint32_t*)g_ctxwt;
        for (int i = tid; i < 256*16; i += 256)
            s_ctx[(i >> 4)*17 + (i & 15)] = cg[i];
        ((float*)(smem + AWOFF))[tid] = alphaw[tid];
    }

    for (int it = 0; it < NSTEP; it++) {
        // ---- P1: U = h @ bigW2t (K=256, N=1536), 48 blocks, no split-K ----
        if (it > 0) {
            if (blk < 48) {
                int bx = blk % 12, by = blk / 12;
                float acc[2][4][4];
                gemm_core<256>(g_h, 256, g_bigw2t, 256, bx*128, by*64, 0, smem, acc);
                epi_partials(acc, g_U, 1536, bx*128, by*64);
            }
            gridbar();
        }

        // ---- P2: MSDA, 1 query per block ----
        msda_one(blk, it, rp, vr, seq, embw, offb, awb, alphab, smem);
        gridbar();

        // ---- P3: gates = [attn|emb] @ W21t (K=512) + U_g + q_gp ; fused LSTM ----
        if (blk < 32) {
            int bx = blk & 7, by = blk >> 3;
            int n0 = bx*128, row0 = by*64;
            float acc[2][4][4];
            gemm_core<512>(g_ae, 512, g_w21t, 512, n0, row0, 0, smem, acc);

            __syncthreads();
            float* sC = (float*)smem;   // [64][128]
            {
                const int lane = tid & 31, warp = tid >> 5;
                const int wm = warp >> 2, wn = warp & 3;
                const int g = lane >> 2, t = lane & 3;
#pragma unroll
                for (int mt = 0; mt < 2; mt++) {
                    int lr = wm*32 + mt*16 + g;
#pragma unroll
                    for (int nt = 0; nt < 4; nt++) {
                        int lc = wn*32 + nt*8 + (t << 1);
                        float* c = acc[mt][nt];
                        sC[lr*128 + lc]     = c[0];  sC[lr*128 + lc + 1]     = c[1];
                        sC[(lr+8)*128 + lc] = c[2];  sC[(lr+8)*128 + lc + 1] = c[3];
                    }
                }
            }
            __syncthreads();
            for (int i = tid; i < 64*32; i += 256) {
                int mloc = i >> 5, dloc = i & 31;
                int q  = row0 + mloc;
                int nb = n0 + dloc*4;
                float4 uv = *(const float4*)&g_U[q*1536 + 512 + nb];
                float4 qv = *(const float4*)&g_qgpc[q*1280 + nb];
                const float* gr = sC + mloc*128 + dloc*4;
                float gi = gr[0] + uv.x + qv.x;
                float gf = gr[1] + uv.y + qv.y;
                float gg = gr[2] + uv.z + qv.z;
                float go = gr[3] + uv.w + qv.w;
                int d = nb >> 2;
                float c  = g_c[q*256 + d];
                float si = 1.f / (1.f + expf(-gi));
                float sf = 1.f / (1.f + expf(-gf));
                float so = 1.f / (1.f + expf(-go));
                float c2 = sf * c + si * tanhf(gg);
                float h2 = so * tanhf(c2);
                g_c[q*256 + d] = c2;
                g_h[q*256 + d] = h2;
                g_hseqb[((size_t)it*NEq + q)*DDim + d] = __float2bfloat16(h2);
            }
        }
        gridbar();
    }
}

// ------------------------- launch -------------------------
extern "C" void kernel_launch(void* const* d_in, const int* in_sizes, int n_in,
                              void* d_out, int out_size)
{
    const int*   seq    = (const int*)  d_in[0];
    const float* query  = (const float*)d_in[1];
    const float* rp     = (const float*)d_in[2];
    const float* enc    = (const float*)d_in[3];
    const float* mask   = (const float*)d_in[4];
    const float* vrr    = (const float*)d_in[5];
    const float* embw   = (const float*)d_in[6];
    const float* logitw = (const float*)d_in[7];
    const float* logitb = (const float*)d_in[8];
    const float* valuew = (const float*)d_in[9];
    const float* valueb = (const float*)d_in[10];
    const float* offw   = (const float*)d_in[11];
    const float* offb   = (const float*)d_in[12];
    const float* aww    = (const float*)d_in[13];
    const float* awb    = (const float*)d_in[14];
    const float* ctxw   = (const float*)d_in[15];
    const float* ctxb   = (const float*)d_in[16];
    const float* hsw    = (const float*)d_in[17];
    const float* hsb    = (const float*)d_in[18];
    const float* alphaw = (const float*)d_in[19];
    const float* alphab = (const float*)d_in[20];
    const float* wih    = (const float*)d_in[21];
    const float* whh    = (const float*)d_in[22];
    float* out = (float*)d_out;

    cudaFuncSetAttribute(gemms_pre,      cudaFuncAttributeMaxDynamicSharedMemorySize, SMEMSZ);
    cudaFuncSetAttribute(loop_kernel,    cudaFuncAttributeMaxDynamicSharedMemorySize, SMEMLOOP);
    cudaFuncSetAttribute(logits_stream1, cudaFuncAttributeMaxDynamicSharedMemorySize, SMEMS2);
    cudaFuncSetAttribute(logits_stream2, cudaFuncAttributeMaxDynamicSharedMemorySize, SMEMS2);

    // idx 0..2 preamble; idx 3 = loop_kernel (ncu displays idx 3)
    prep_transposes<<<936, 256>>>(logitw, wih, whh, offw, aww, hsw);
    build_small    <<<512, 256>>>(ctxw, valuew, hsb, ctxb);
    gemms_pre      <<<520, 256, SMEMSZ>>>(enc, valueb, mask, query);

    loop_kernel<<<LOOPBLK, 256, SMEMLOOP>>>(rp, vrr, seq, embw, offb, awb, alphaw, alphab);

    logits_stream1<<<dim3(79, 40), 256, SMEMS2>>>(logitb);
    lse_reduce    <<<MTOT/8, 256>>>();
    logits_stream2<<<dim3(79, 40), 256, SMEMS2>>>(logitb, out);
}

// round 11
// speedup vs baseline: 1.1787x; 1.1787x over previous
#include <cuda_runtime.h>
#include <cuda_bf16.h>
#include <math.h>
#include <stdint.h>

#define NB    8
#define NEq   256
#define SSq   21
#define NSTEP 20
#define DDim  256
#define HHn   8
#define HDn   32
#define VVn   10000
#define TTn   1920
#define VPAD  10112
#define MTOT  (NSTEP*NEq)   // 5120
#define LOOPBLK 256
#define BST   12
#define SMEMSZ  (33792 + 2*128*BST*4)   // 46080 (GEMM scratch)
#define CTXOFF  46080
#define AWOFF   (CTXOFF + 17408)        // 63488
#define SMEMLOOP (AWOFF + 1024)         // 64512
#define SMEMS2  (2*128*12*4*2)          // 24576

// ------------------------- device scratch -------------------------
__device__ __align__(16) float g_value [NB*HHn*TTn*HDn];
__device__ __align__(16) float g_U     [4*NEq*1536];  // split-K4 partials: h@[offaw|hsw|whh_gi]
__device__ __align__(16) float g_gatesp[8*NEq*1024];  // split-K8 partials: [attn|emb]@w21t
__device__ __align__(16) float g_ae    [NEq*512];     // [attn | emb]
__device__ __align__(16) float g_qgpc  [NEq*1280];    // [query@wih_q_gi (1024) | query@offaw_bot (256)]
__device__ __align__(16) float g_h     [NEq*DDim];
__device__ __align__(16) float g_c     [NEq*DDim];
__device__ __align__(16) float g_hsbc  [256];
__device__ __align__(16) float g_lss   [MTOT*80];
__device__ __align__(16) float g_lse   [MTOT];
__device__ __align__(16) __nv_bfloat16 g_hseqb  [MTOT*DDim];
__device__ __align__(16) __nv_bfloat16 g_bigw2t [1536*256];
__device__ __align__(16) __nv_bfloat16 g_w21t   [1024*512];
__device__ __align__(16) __nv_bfloat16 g_wct    [1280*256];
__device__ __align__(16) __nv_bfloat16 g_logitwt[VPAD*256];
__device__ __align__(16) __nv_bfloat16 g_ctxwt  [256*32];
__device__ __align__(16) __nv_bfloat16 g_valuewt[256*256];

// store/poll grid barrier state (no atomics)
__device__ volatile unsigned g_flags[LOOPBLK];
__device__ volatile unsigned g_bar_gen;

// ------------------------- helpers -------------------------
__device__ __forceinline__ float tanha(float x) {
    float y; asm("tanh.approx.f32 %0, %1;" : "=f"(y) : "f"(x)); return y;
}
__device__ __forceinline__ void mma16816(float* c, const uint32_t* a, const uint32_t* b) {
    asm volatile(
        "mma.sync.aligned.m16n8k16.row.col.f32.bf16.bf16.f32 "
        "{%0,%1,%2,%3}, {%4,%5,%6,%7}, {%8,%9}, {%0,%1,%2,%3};"
        : "+f"(c[0]), "+f"(c[1]), "+f"(c[2]), "+f"(c[3])
        : "r"(a[0]), "r"(a[1]), "r"(a[2]), "r"(a[3]), "r"(b[0]), "r"(b[1]));
}
__device__ __forceinline__ void cpasync16(uint32_t dst, const void* src) {
    asm volatile("cp.async.cg.shared.global [%0], [%1], 16;" :: "r"(dst), "l"(src));
}

// grid barrier: per-block volatile flag store; block 0 collects (1 flag/thread),
// then single release store. gen is monotone across graph replays (wrap-safe compare).
__device__ __forceinline__ void gridbar(unsigned gen) {
    __syncthreads();
    if (threadIdx.x == 0) {
        __threadfence();
        g_flags[blockIdx.x] = gen;
    }
    if (blockIdx.x == 0) {
        while ((int)(g_flags[threadIdx.x] - gen) < 0) { }
        __syncthreads();
        if (threadIdx.x == 0) { __threadfence(); g_bar_gen = gen; }
    }
    if (threadIdx.x == 0) {
        while ((int)(g_bar_gen - gen) < 0) { }
        __threadfence();
    }
    __syncthreads();
}

// ------------------------- GEMM mainloop (64x128 tile, 8 warps) -------------------------
template<int KCHUNK>
__device__ __forceinline__ void gemm_core(
    const float* __restrict__ A, int lda,
    const __nv_bfloat16* __restrict__ Wt, int ldw,
    int n0, int row0, int kbeg, char* smem, float acc[2][4][4])
{
    uint32_t* Asw = (uint32_t*)smem;                 // [64][132] words
    uint32_t* Bsw = (uint32_t*)(smem + 33792);       // [2][128][BST] words
    const int SAW = 132;
    const int NKT = KCHUNK >> 4;
    constexpr int KC = (KCHUNK < 256) ? KCHUNK : 256;

    const int tid  = threadIdx.x;
    const int lane = tid & 31, warp = tid >> 5;
    const int wm = warp >> 2, wn = warp & 3;
    const int g = lane >> 2, t = lane & 3;
    const int bn = tid >> 1, bq = (tid & 1) << 3;
    const uint32_t bsm = (uint32_t)__cvta_generic_to_shared(Bsw);

    cpasync16(bsm + (uint32_t)((bn*BST + (bq>>1))*4),
              Wt + (size_t)(n0 + bn) * ldw + kbeg + bq);
    asm volatile("cp.async.commit_group;");

#pragma unroll
    for (int i = 0; i < 2; i++)
#pragma unroll
        for (int j = 0; j < 4; j++)
#pragma unroll
            for (int q = 0; q < 4; q++) acc[i][j][q] = 0.f;

#pragma unroll 1
    for (int ksg = 0; ksg < NKT; ksg++) {
        __syncthreads();
        if ((ksg & 15) == 0) {
            int kA = kbeg + ((ksg >> 4) << 8);
#pragma unroll
            for (int idx = tid * 4; idx < 64 * KC; idx += 1024) {
                int r = idx / KC, cc = idx % KC;
                float4 v = *(const float4*)(A + (size_t)(row0 + r) * lda + kA + cc);
                __nv_bfloat162 p0 = __float22bfloat162_rn(make_float2(v.x, v.y));
                __nv_bfloat162 p1 = __float22bfloat162_rn(make_float2(v.z, v.w));
                Asw[r * SAW + (cc >> 1)]     = *(uint32_t*)&p0;
                Asw[r * SAW + (cc >> 1) + 1] = *(uint32_t*)&p1;
            }
        }
        if (ksg + 1 < NKT)
            cpasync16(bsm + (uint32_t)(((((ksg+1)&1)*128*BST) + bn*BST + (bq>>1))*4),
                      Wt + (size_t)(n0 + bn) * ldw + kbeg + (ksg + 1) * 16 + bq);
        asm volatile("cp.async.commit_group;");
        asm volatile("cp.async.wait_group 1;");
        __syncthreads();

        const int wo = (ksg & 15) * 8;
        uint32_t a[2][4];
#pragma unroll
        for (int mt = 0; mt < 2; mt++) {
            const uint32_t* ap = Asw + (wm*32 + mt*16 + g) * SAW + wo + t;
            a[mt][0] = ap[0];
            a[mt][1] = ap[8 * SAW];
            a[mt][2] = ap[4];
            a[mt][3] = ap[8 * SAW + 4];
        }
        const uint32_t* bbase = Bsw + (ksg & 1) * 128 * BST;
        uint32_t bf[4][2];
#pragma unroll
        for (int nt = 0; nt < 4; nt++) {
            const uint32_t* bp = bbase + (wn*32 + nt*8 + g) * BST + t;
            bf[nt][0] = bp[0];
            bf[nt][1] = bp[4];
        }
#pragma unroll
        for (int mt = 0; mt < 2; mt++)
#pragma unroll
            for (int nt = 0; nt < 4; nt++)
                mma16816(acc[mt][nt], a[mt], bf[nt]);
    }
}

__device__ __forceinline__ void epi_partials(float acc[2][4][4], float* C, int N,
                                             int n0, int row0)
{
    const int lane = threadIdx.x & 31, warp = threadIdx.x >> 5;
    const int wm = warp >> 2, wn = warp & 3;
    const int g = lane >> 2, t = lane & 3;
#pragma unroll
    for (int mt = 0; mt < 2; mt++) {
        int m = row0 + wm*32 + mt*16 + g;
#pragma unroll
        for (int nt = 0; nt < 4; nt++) {
            int n = n0 + wn*32 + nt*8 + (t << 1);
            float* c = acc[mt][nt];
            *(float2*)(C + (size_t)m * N + n)       = make_float2(c[0], c[1]);
            *(float2*)(C + (size_t)(m + 8) * N + n) = make_float2(c[2], c[3]);
        }
    }
}

// ------------------------- fused preamble GEMMs: value + const (query@wct) -------------
__global__ __launch_bounds__(256, 2)
void gemms_pre(const float* __restrict__ enc, const float* __restrict__ valueb,
               const float* __restrict__ mask, const float* __restrict__ query)
{
    extern __shared__ char smem[];
    float acc[2][4][4];
    const int blk = blockIdx.x;
    if (blk < 480) {
        const int bx = blk & 1, by = blk >> 1;
        const int n0 = bx*128, row0 = by*64;
        gemm_core<256>(enc, 256, g_valuewt, 256, n0, row0, 0, smem, acc);
        const int lane = threadIdx.x & 31, warp = threadIdx.x >> 5;
        const int wm = warp >> 2, wn = warp & 3;
        const int g = lane >> 2, t = lane & 3;
#pragma unroll
        for (int mt = 0; mt < 2; mt++) {
#pragma unroll
            for (int mi = 0; mi < 2; mi++) {
                int m  = row0 + wm*32 + mt*16 + g + mi*8;
                int b  = m / TTn;
                int tt = m - b * TTn;
                float mk = mask[m];
#pragma unroll
                for (int nt = 0; nt < 4; nt++) {
                    int n = n0 + wn*32 + nt*8 + (t << 1);
                    int h = n >> 5, hd = n & 31;
                    float* c = acc[mt][nt];
                    float v0 = (c[mi*2]   + valueb[n])     * mk;
                    float v1 = (c[mi*2+1] + valueb[n + 1]) * mk;
                    *(float2*)(g_value + (((size_t)(b*HHn + h))*TTn + tt)*HDn + hd)
                        = make_float2(v0, v1);
                }
            }
        }
    } else {
        const int cb = blk - 480;                // 40 blocks: qgpc = query @ wct
        const int bx = cb % 10, by = cb / 10;
        gemm_core<256>(query, 256, g_wct, 256, bx*128, by*64, 0, smem, acc);
        epi_partials(acc, g_qgpc, 1280, bx*128, by*64);
    }
}

// ------------------------- streaming 128x128 GEMM core (logits) -------------------------
__device__ __forceinline__ void stream_core(const __nv_bfloat16* __restrict__ Ag0,
                                            const __nv_bfloat16* __restrict__ Bg0,
                                            char* smem, float acc[4][4][4])
{
    uint32_t* As = (uint32_t*)smem;
    uint32_t* Bs = (uint32_t*)(smem + 12288);
    const int tid = threadIdx.x;
    const int lane = tid & 31, warp = tid >> 5;
    const int wm = warp >> 2, wn = warp & 3;
    const int g = lane >> 2, t = lane & 3;
    const int lr = tid >> 1, lc = (tid & 1) << 3;
    const uint32_t asmb = (uint32_t)__cvta_generic_to_shared(As);
    const uint32_t bsmb = (uint32_t)__cvta_generic_to_shared(Bs);
    const uint32_t loff = (uint32_t)((lr*12 + (lc>>1))*4);
    const __nv_bfloat16* Ag = Ag0 + (size_t)lr*256 + lc;
    const __nv_bfloat16* Bg = Bg0 + (size_t)lr*256 + lc;

    cpasync16(asmb + loff, Ag);
    cpasync16(bsmb + loff, Bg);
    asm volatile("cp.async.commit_group;");

#pragma unroll
    for (int i = 0; i < 4; i++)
#pragma unroll
        for (int j = 0; j < 4; j++)
#pragma unroll
            for (int q = 0; q < 4; q++) acc[i][j][q] = 0.f;

#pragma unroll 1
    for (int ks = 0; ks < 16; ks++) {
        __syncthreads();
        if (ks + 1 < 16) {
            uint32_t bo = (uint32_t)(((ks + 1) & 1) * 6144);
            cpasync16(asmb + bo + loff, Ag + (ks + 1) * 16);
            cpasync16(bsmb + bo + loff, Bg + (ks + 1) * 16);
        }
        asm volatile("cp.async.commit_group;");
        asm volatile("cp.async.wait_group 1;");
        __syncthreads();

        const uint32_t* Ab = As + (ks & 1) * 1536;
        const uint32_t* Bb = Bs + (ks & 1) * 1536;
        uint32_t a[4][4];
#pragma unroll
        for (int mt = 0; mt < 4; mt++) {
            const uint32_t* ap = Ab + (wm*64 + mt*16 + g) * 12 + t;
            a[mt][0] = ap[0];
            a[mt][1] = ap[8 * 12];
            a[mt][2] = ap[4];
            a[mt][3] = ap[8 * 12 + 4];
        }
        uint32_t b[4][2];
#pragma unroll
        for (int nt = 0; nt < 4; nt++) {
            const uint32_t* bp = Bb + (wn*32 + nt*8 + g) * 12 + t;
            b[nt][0] = bp[0];
            b[nt][1] = bp[4];
        }
#pragma unroll
        for (int mt = 0; mt < 4; mt++)
#pragma unroll
            for (int nt = 0; nt < 4; nt++)
                mma16816(acc[mt][nt], a[mt], b[nt]);
    }
}

__global__ __launch_bounds__(256, 2)
void logits_stream1(const float* __restrict__ logitb)
{
    extern __shared__ char smem[];
    float acc[4][4][4];
    const int n0 = blockIdx.x * 128, row0 = blockIdx.y * 128;
    stream_core(g_hseqb + (size_t)row0*256, g_logitwt + (size_t)n0*256, smem, acc);

    const int tid = threadIdx.x;
    const int lane = tid & 31, warp = tid >> 5;
    const int wm = warp >> 2, wn = warp & 3;
    const int g = lane >> 2, t = lane & 3;

    float bias_r[4][2];
#pragma unroll
    for (int nt = 0; nt < 4; nt++) {
        int n = n0 + wn*32 + nt*8 + (t << 1);
        bias_r[nt][0] = (n     < VVn) ? logitb[n]     : 0.f;
        bias_r[nt][1] = (n + 1 < VVn) ? logitb[n + 1] : 0.f;
    }

    __syncthreads();
    float* s_ps = (float*)smem;
#pragma unroll
    for (int mt = 0; mt < 4; mt++) {
#pragma unroll
        for (int mi = 0; mi < 2; mi++) {
            int mloc = wm*64 + mt*16 + g + mi*8;
            float ls = 0.f;
#pragma unroll
            for (int nt = 0; nt < 4; nt++) {
                int n = n0 + wn*32 + nt*8 + (t << 1);
#pragma unroll
                for (int e = 0; e < 2; e++)
                    if (n + e < VVn)
                        ls += __expf(acc[mt][nt][mi*2 + e] + bias_r[nt][e]);
            }
            ls += __shfl_xor_sync(0xffffffffu, ls, 1);
            ls += __shfl_xor_sync(0xffffffffu, ls, 2);
            if (t == 0) s_ps[mloc*4 + wn] = ls;
        }
    }
    __syncthreads();
    if (tid < 128) {
        float ls = s_ps[tid*4] + s_ps[tid*4+1] + s_ps[tid*4+2] + s_ps[tid*4+3];
        g_lss[(size_t)(row0 + tid)*80 + blockIdx.x] = ls;
    }
}

__global__ __launch_bounds__(256)
void lse_reduce()
{
    const int w = threadIdx.x >> 5, lane = threadIdx.x & 31;
    const int m = blockIdx.x * 8 + w;
    float s = 0.f;
    const float* p = g_lss + (size_t)m * 80;
    if (lane < 79)       s  = p[lane];
    if (lane + 32 < 79)  s += p[lane + 32];
    if (lane + 64 < 79)  s += p[lane + 64];
#pragma unroll
    for (int o = 16; o; o >>= 1) s += __shfl_xor_sync(0xffffffffu, s, o);
    if (lane == 0) g_lse[m] = logf(s);
}

__global__ __launch_bounds__(256, 2)
void logits_stream2(const float* __restrict__ logitb, float* __restrict__ out)
{
    extern __shared__ char smem[];
    float acc[4][4][4];
    const int n0 = blockIdx.x * 128, row0 = blockIdx.y * 128;
    stream_core(g_hseqb + (size_t)row0*256, g_logitwt + (size_t)n0*256, smem, acc);

    const int lane = threadIdx.x & 31, warp = threadIdx.x >> 5;
    const int wm = warp >> 2, wn = warp & 3;
    const int g = lane >> 2, t = lane & 3;

#pragma unroll
    for (int mt = 0; mt < 4; mt++) {
#pragma unroll
        for (int mi = 0; mi < 2; mi++) {
            int m  = row0 + wm*64 + mt*16 + g + mi*8;
            int q  = m & 255, st = m >> 8;
            float lse = g_lse[m];
            float* orow = out + ((size_t)q * NSTEP + st) * VVn;
#pragma unroll
            for (int nt = 0; nt < 4; nt++) {
                int n = n0 + wn*32 + nt*8 + (t << 1);
                if (n < VVn) {
                    float* c = acc[mt][nt];
                    *(float2*)(orow + n) = make_float2(c[mi*2]   + logitb[n]   - lse,
                                                       c[mi*2+1] + logitb[n+1] - lse);
                }
            }
        }
    }
}

// ------------------------- preamble: all weight transposes -------------------------
__global__ __launch_bounds__(256)
void prep_transposes(const float* __restrict__ lw,
                     const float* __restrict__ wih, const float* __restrict__ whh,
                     const float* __restrict__ offw, const float* __restrict__ aww,
                     const float* __restrict__ hsw)
{
    __shared__ float s_t[64][65];
    const int blk = blockIdx.x;
    const int tx = threadIdx.x & 63, ty = threadIdx.x >> 6;

    if (blk < 632) {                                    // logitwt: 158 x 4
        const int n0 = (blk % 158) * 64, k0 = (blk / 158) * 64;
#pragma unroll
        for (int rr = ty; rr < 64; rr += 4)
            s_t[rr][tx] = (n0 + tx < VVn) ? lw[(size_t)(k0 + rr) * VVn + n0 + tx] : 0.f;
        __syncthreads();
#pragma unroll
        for (int rr = ty; rr < 64; rr += 4)
            g_logitwt[(size_t)(n0 + rr) * 256 + k0 + tx] = __float2bfloat16(s_t[tx][rr]);
    } else if (blk < 760) {                             // w21t: 16 n x 8 k tiles
        const int idx = blk - 632;
        const int n0 = (idx & 15) * 64, k0 = (idx >> 4) * 64;
#pragma unroll
        for (int rr = ty; rr < 64; rr += 4) {
            int k = k0 + rr, n = n0 + tx;
            int j = (n & 3) * 256 + (n >> 2);
            s_t[rr][tx] = (k < 256) ? wih[(size_t)(256 + k) * 1024 + j]
                                    : wih[(size_t)(k - 256) * 1024 + j];
        }
        __syncthreads();
#pragma unroll
        for (int rr = ty; rr < 64; rr += 4)
            g_w21t[(size_t)(n0 + rr) * 512 + k0 + tx] = __float2bfloat16(s_t[tx][rr]);
    } else if (blk < 856) {                             // bigw2t: 24 n x 4 k tiles
        const int idx = blk - 760;
        const int n0 = (idx % 24) * 64, k0 = (idx / 24) * 64;
#pragma unroll
        for (int rr = ty; rr < 64; rr += 4) {
            int k = k0 + rr, n = n0 + tx;
            float v;
            if (n < 128)      v = offw[k*128 + n];
            else if (n < 256) v = aww[k*128 + (n - 128)];
            else if (n < 512) v = hsw[k*256 + (n - 256)];
            else {
                int m = n - 512;
                v = whh[(size_t)k * 1024 + (m & 3) * 256 + (m >> 2)];
            }
            s_t[rr][tx] = v;
        }
        __syncthreads();
#pragma unroll
        for (int rr = ty; rr < 64; rr += 4)
            g_bigw2t[(size_t)(n0 + rr) * 256 + k0 + tx] = __float2bfloat16(s_t[tx][rr]);
    } else {                                            // wct: 20 n x 4 k tiles
        const int idx = blk - 856;
        const int n0 = (idx % 20) * 64, k0 = (idx / 20) * 64;
#pragma unroll
        for (int rr = ty; rr < 64; rr += 4) {
            int k = k0 + rr, n = n0 + tx;
            float v;
            if (n < 1024)
                v = wih[(size_t)(512 + k) * 1024 + (n & 3) * 256 + (n >> 2)];
            else {
                int m = n - 1024;
                v = (m < 128) ? offw[(256 + k)*128 + m] : aww[(256 + k)*128 + (m - 128)];
            }
            s_t[rr][tx] = v;
        }
        __syncthreads();
#pragma unroll
        for (int rr = ty; rr < 64; rr += 4)
            g_wct[(size_t)(n0 + rr) * 256 + k0 + tx] = __float2bfloat16(s_t[tx][rr]);
    }
}

__global__ __launch_bounds__(256)
void build_small(const float* __restrict__ ctxw, const float* __restrict__ valuew,
                 const float* __restrict__ hsb,  const float* __restrict__ ctxb)
{
    const int blk = blockIdx.x, tid = threadIdx.x;
    if (blk < 256) {
        int q = blk;
        g_h[q*256 + tid] = 0.f;
        g_c[q*256 + tid] = 0.f;
        if (q == 0) g_hsbc[tid] = hsb[tid] + ctxb[tid];
    } else {
        int i = (blk - 256) * 256 + tid;                // 0..65535
        if (i < 256*32) {
            int n = i >> 5, k = i & 31;
            g_ctxwt[n*32 + k] = __float2bfloat16(ctxw[k*256 + n]);
        }
        int n = i >> 8, k = i & 255;
        g_valuewt[n*256 + k] = __float2bfloat16(valuew[k*256 + n]);
    }
}

// ------------------------- fused MSDA (one query per block; persistent ctx) -------------
__device__ void msda_one(int n, int step,
                         const float* __restrict__ rp,   const float* __restrict__ vr,
                         const int*   __restrict__ seq,  const float* __restrict__ embw,
                         const float* __restrict__ offb, const float* __restrict__ awb,
                         const float* __restrict__ alphab, char* smem)
{
    uint32_t* s_hsampb = (uint32_t*)smem;              // [128][17]
    float* s_hb    = (float*)(smem + 8704);
    float* s_off   = (float*)(smem + 9728);
    float* s_aw    = (float*)(smem + 10240);
    float* s_alpha = (float*)(smem + 10752);
    float* s_wgt   = (float*)(smem + 11264);
    const uint32_t* s_ctx = (const uint32_t*)(smem + CTXOFF);
    const float*    s_aww = (const float*)(smem + AWOFF);

    const int b    = n >> 5;
    const int tid  = threadIdx.x;
    const int lane = tid & 31;
    const int w    = tid >> 5;

    __syncthreads();

    {
        int tok = (step == 0) ? 1 : seq[n*SSq + step - 1];
        g_ae[n*512 + 256 + tid] = embw[(size_t)tok * DDim + tid];
        float s = 0.f;
#pragma unroll
        for (int zu = 0; zu < 4; zu++)
            s += g_U[((size_t)zu*NEq + n)*1536 + 256 + tid];
        s_hb[tid] = s + g_hsbc[tid];
    }
    if (tid < 128) {
        float so = 0.f, sa = 0.f;
#pragma unroll
        for (int zu = 0; zu < 4; zu++) {
            so += g_U[((size_t)zu*NEq + n)*1536 + tid];
            sa += g_U[((size_t)zu*NEq + n)*1536 + 128 + tid];
        }
        so += g_qgpc[n*1280 + 1024 + tid] + offb[tid];
        sa += g_qgpc[n*1280 + 1152 + tid] + awb[tid];
        s_off[tid] = so;
        float m = sa;
#pragma unroll
        for (int o = 8; o; o >>= 1) m = fmaxf(m, __shfl_xor_sync(0xffffffffu, m, o));
        float e = __expf(sa - m);
        float sm = e;
#pragma unroll
        for (int o = 8; o; o >>= 1) sm += __shfl_xor_sync(0xffffffffu, sm, o);
        s_aw[tid] = e / sm;
    }
    __syncthreads();

    {
        const float rpn = rp[n];
        __nv_bfloat16* hs = (__nv_bfloat16*)s_hsampb;
#pragma unroll
        for (int i = 0; i < 16; i++) {
            int r = (w << 4) + i;
            int h = r >> 4;
            int l = (r >> 2) & 3;
            int shape_l = 1024 >> l;
            int start_l = 2048 - (2048 >> l);
            float refl = rpn * vr[b*4 + l];
            float x = refl * (float)shape_l + s_off[r] - 0.5f;
            float x0f = floorf(x);
            float wf = x - x0f;
            int x0 = (int)x0f;
            const float* vbase = g_value + (((size_t)(b*HHn + h))*TTn + start_l) * HDn;
            float g0 = (x0 >= 0     && x0     < shape_l) ? vbase[(size_t)x0     * HDn + lane] : 0.f;
            float g1 = (x0 + 1 >= 0 && x0 + 1 < shape_l) ? vbase[(size_t)(x0+1) * HDn + lane] : 0.f;
            hs[r*34 + lane] = __float2bfloat16((g0 * (1.f - wf) + g1 * wf) * s_aw[r]);
        }
    }
    __syncthreads();

    {
        const int g = lane >> 2, t = lane & 3;
        const int r0 = w << 4;
        const float ab = alphab[0];

        uint32_t a[2][4];
#pragma unroll
        for (int ks = 0; ks < 2; ks++) {
            const uint32_t* ap = s_hsampb + (r0 + g) * 17 + ks*8 + t;
            a[ks][0] = ap[0];
            a[ks][1] = ap[8 * 17];
            a[ks][2] = ap[4];
            a[ks][3] = ap[8 * 17 + 4];
        }
        float p0 = 0.f, p1 = 0.f;
#pragma unroll
        for (int nb = 0; nb < 256; nb += 8) {
            float c[4] = {0.f, 0.f, 0.f, 0.f};
#pragma unroll
            for (int ks = 0; ks < 2; ks++) {
                const uint32_t* bp = s_ctx + (nb + g) * 17 + ks*8 + t;
                uint32_t bf2[2] = { bp[0], bp[4] };
                mma16816(c, a[ks], bf2);
            }
            int col = nb + (t << 1);
            float hb0 = s_hb[col], hb1 = s_hb[col + 1];
            float aw0 = s_aww[col], aw1 = s_aww[col + 1];
            p0 = fmaf(tanha(c[0] + hb0), aw0, fmaf(tanha(c[1] + hb1), aw1, p0));
            p1 = fmaf(tanha(c[2] + hb0), aw0, fmaf(tanha(c[3] + hb1), aw1, p1));
        }
        p0 += __shfl_xor_sync(0xffffffffu, p0, 1);
        p0 += __shfl_xor_sync(0xffffffffu, p0, 2);
        p1 += __shfl_xor_sync(0xffffffffu, p1, 1);
        p1 += __shfl_xor_sync(0xffffffffu, p1, 2);
        if (t == 0) {
            s_alpha[r0 + g]     = p0 + ab;
            s_alpha[r0 + g + 8] = p1 + ab;
        }
    }
    __syncthreads();

    if (tid < 128) {
        float v = s_alpha[tid];
        float m = v;
#pragma unroll
        for (int o = 8; o; o >>= 1) m = fmaxf(m, __shfl_xor_sync(0xffffffffu, m, o));
        float e = __expf(v - m);
        float sm = e;
#pragma unroll
        for (int o = 8; o; o >>= 1) sm += __shfl_xor_sync(0xffffffffu, sm, o);
        s_wgt[tid] = e / sm;
    }
    __syncthreads();

    {
        int h = tid >> 5, hd = tid & 31;
        const __nv_bfloat16* hs = (const __nv_bfloat16*)s_hsampb;
        float res = 0.f;
#pragma unroll
        for (int lp = 0; lp < 16; lp++)
            res = fmaf(s_wgt[(h << 4) + lp],
                       __bfloat162float(hs[((h << 4) + lp)*34 + hd]), res);
        g_ae[n*512 + tid] = res;
    }
}

// ------------------------- persistent recurrent loop (4 barriers/step) -------------------
__global__ __launch_bounds__(256, 2)
void loop_kernel(const float* __restrict__ rp,   const float* __restrict__ vr,
                 const int*   __restrict__ seq,  const float* __restrict__ embw,
                 const float* __restrict__ offb, const float* __restrict__ awb,
                 const float* __restrict__ alphaw, const float* __restrict__ alphab)
{
    extern __shared__ char smem[];
    const int blk = blockIdx.x;
    const int tid = threadIdx.x;
    unsigned bgen = g_bar_gen;     // all blocks read the same pre-loop value

    // load persistent ctx + alphaw once
    {
        uint32_t* s_ctx = (uint32_t*)(smem + CTXOFF);
        const uint32_t* cg = (const uint32_t*)g_ctxwt;
        for (int i = tid; i < 256*16; i += 256)
            s_ctx[(i >> 4)*17 + (i & 15)] = cg[i];
        ((float*)(smem + AWOFF))[tid] = alphaw[tid];
    }

    for (int it = 0; it <= NSTEP; it++) {
        if (it > 0) {
            // ---- P0: LSTM (one query per block): sum 8 gate partials + 4 U partials + qgpc
            {
                int q = blk, d = tid;
                float4 s = make_float4(0.f, 0.f, 0.f, 0.f);
#pragma unroll
                for (int z = 0; z < 8; z++) {
                    float4 gp = *(const float4*)&g_gatesp[((size_t)z*NEq + q)*1024 + d*4];
                    s.x += gp.x; s.y += gp.y; s.z += gp.z; s.w += gp.w;
                }
#pragma unroll
                for (int zu = 0; zu < 4; zu++) {
                    float4 uv = *(const float4*)&g_U[((size_t)zu*NEq + q)*1536 + 512 + d*4];
                    s.x += uv.x; s.y += uv.y; s.z += uv.z; s.w += uv.w;
                }
                float4 qv = *(const float4*)&g_qgpc[q*1280 + d*4];
                float gi = s.x + qv.x, gf = s.y + qv.y, gg = s.z + qv.z, go = s.w + qv.w;
                float c  = g_c[q*256 + d];
                float si = 1.f / (1.f + expf(-gi));
                float sf = 1.f / (1.f + expf(-gf));
                float so = 1.f / (1.f + expf(-go));
                float c2 = sf * c + si * tanhf(gg);
                float h2 = so * tanhf(c2);
                g_c[q*256 + d] = c2;
                g_h[q*256 + d] = h2;
                g_hseqb[((size_t)(it-1)*NEq + q)*DDim + d] = __float2bfloat16(h2);
            }
            if (it == NSTEP) break;
            gridbar(++bgen);
        }

        // ---- P1: U = h @ bigw2t (256x1536, K=256) split-K4 -> 192 blocks x 4 iters ----
        if (blk < 192) {
            int bz = blk / 48, r = blk % 48;
            int bx = r % 12, by = r / 12;
            float acc[2][4][4];
            gemm_core<64>(g_h, 256, g_bigw2t, 256, bx*128, by*64, bz*64, smem, acc);
            epi_partials(acc, g_U + (size_t)bz*NEq*1536, 1536, bx*128, by*64);
        }
        gridbar(++bgen);

        // ---- P2: MSDA, 1 query per block ----
        msda_one(blk, it, rp, vr, seq, embw, offb, awb, alphab, smem);
        gridbar(++bgen);

        // ---- P3: gates_part = [attn|emb] @ w21t (256x1024, K=512) split-K8 -> 256 blocks
        {
            int bz = blk >> 5, r = blk & 31;
            int bx = r & 7, by = r >> 3;
            float acc[2][4][4];
            gemm_core<64>(g_ae, 512, g_w21t, 512, bx*128, by*64, bz*64, smem, acc);
            epi_partials(acc, g_gatesp + (size_t)bz*NEq*1024, 1024, bx*128, by*64);
        }
        gridbar(++bgen);
    }
}

// ------------------------- launch -------------------------
extern "C" void kernel_launch(void* const* d_in, const int* in_sizes, int n_in,
                              void* d_out, int out_size)
{
    const int*   seq    = (const int*)  d_in[0];
    const float* query  = (const float*)d_in[1];
    const float* rp     = (const float*)d_in[2];
    const float* enc    = (const float*)d_in[3];
    const float* mask   = (const float*)d_in[4];
    const float* vrr    = (const float*)d_in[5];
    const float* embw   = (const float*)d_in[6];
    const float* logitw = (const float*)d_in[7];
    const float* logitb = (const float*)d_in[8];
    const float* valuew = (const float*)d_in[9];
    const float* valueb = (const float*)d_in[10];
    const float* offw   = (const float*)d_in[11];
    const float* offb   = (const float*)d_in[12];
    const float* aww    = (const float*)d_in[13];
    const float* awb    = (const float*)d_in[14];
    const float* ctxw   = (const float*)d_in[15];
    const float* ctxb   = (const float*)d_in[16];
    const float* hsw    = (const float*)d_in[17];
    const float* hsb    = (const float*)d_in[18];
    const float* alphaw = (const float*)d_in[19];
    const float* alphab = (const float*)d_in[20];
    const float* wih    = (const float*)d_in[21];
    const float* whh    = (const float*)d_in[22];
    float* out = (float*)d_out;

    cudaFuncSetAttribute(gemms_pre,      cudaFuncAttributeMaxDynamicSharedMemorySize, SMEMSZ);
    cudaFuncSetAttribute(loop_kernel,    cudaFuncAttributeMaxDynamicSharedMemorySize, SMEMLOOP);
    cudaFuncSetAttribute(logits_stream1, cudaFuncAttributeMaxDynamicSharedMemorySize, SMEMS2);
    cudaFuncSetAttribute(logits_stream2, cudaFuncAttributeMaxDynamicSharedMemorySize, SMEMS2);

    // idx 0..2 preamble; idx 3 = loop_kernel (ncu displays idx 3)
    prep_transposes<<<936, 256>>>(logitw, wih, whh, offw, aww, hsw);
    build_small    <<<512, 256>>>(ctxw, valuew, hsb, ctxb);
    gemms_pre      <<<520, 256, SMEMSZ>>>(enc, valueb, mask, query);

    loop_kernel<<<LOOPBLK, 256, SMEMLOOP>>>(rp, vrr, seq, embw, offb, awb, alphaw, alphab);

    logits_stream1<<<dim3(79, 40), 256, SMEMS2>>>(logitb);
    lse_reduce    <<<MTOT/8, 256>>>();
    logits_stream2<<<dim3(79, 40), 256, SMEMS2>>>(logitb, out);
}

// round 12
// speedup vs baseline: 1.2733x; 1.0803x over previous
#include <cuda_runtime.h>
#include <cuda_bf16.h>
#include <math.h>
#include <stdint.h>

#define NB    8
#define NEq   256
#define SSq   21
#define NSTEP 20
#define DDim  256
#define HHn   8
#define HDn   32
#define VVn   10000
#define TTn   1920
#define VPAD  10112
#define MTOT  (NSTEP*NEq)   // 5120
#define LOOPBLK 256
#define NGRP  4
#define GBLK  64            // blocks (and queries) per group
#define BST   12
#define SMEMSZ  (33792 + 2*128*BST*4)   // 46080 (GEMM scratch)
#define CTXOFF  46080
#define AWOFF   (CTXOFF + 17408)        // 63488
#define SMEMLOOP (AWOFF + 1024)         // 64512
#define SMEMS2  (2*128*12*4*2)          // 24576

// ------------------------- device scratch -------------------------
__device__ __align__(16) float g_value [NB*HHn*TTn*HDn];
__device__ __align__(16) float g_U     [4*NEq*1536];  // split-K4 partials
__device__ __align__(16) float g_gatesp[8*NEq*1024];  // split-K8 partials
__device__ __align__(16) float g_ae    [NEq*512];
__device__ __align__(16) float g_qgpc  [NEq*1280];
__device__ __align__(16) float g_h     [NEq*DDim];
__device__ __align__(16) float g_c     [NEq*DDim];
__device__ __align__(16) float g_hsbc  [256];
__device__ __align__(16) float g_lss   [MTOT*80];
__device__ __align__(16) float g_lse   [MTOT];
__device__ __align__(16) __nv_bfloat16 g_hseqb  [MTOT*DDim];
__device__ __align__(16) __nv_bfloat16 g_bigw2t [1536*256];
__device__ __align__(16) __nv_bfloat16 g_w21t   [1024*512];
__device__ __align__(16) __nv_bfloat16 g_wct    [1280*256];
__device__ __align__(16) __nv_bfloat16 g_logitwt[VPAD*256];
__device__ __align__(16) __nv_bfloat16 g_ctxwt  [256*32];
__device__ __align__(16) __nv_bfloat16 g_valuewt[256*256];

// per-group barrier state (padded to distinct 128B lines)
__device__ unsigned g_gcnt[NGRP*32];
__device__ volatile unsigned g_ggen[NGRP*32];

// ------------------------- helpers -------------------------
__device__ __forceinline__ float tanha(float x) {
    float y; asm("tanh.approx.f32 %0, %1;" : "=f"(y) : "f"(x)); return y;
}
__device__ __forceinline__ void mma16816(float* c, const uint32_t* a, const uint32_t* b) {
    asm volatile(
        "mma.sync.aligned.m16n8k16.row.col.f32.bf16.bf16.f32 "
        "{%0,%1,%2,%3}, {%4,%5,%6,%7}, {%8,%9}, {%0,%1,%2,%3};"
        : "+f"(c[0]), "+f"(c[1]), "+f"(c[2]), "+f"(c[3])
        : "r"(a[0]), "r"(a[1]), "r"(a[2]), "r"(a[3]), "r"(b[0]), "r"(b[1]));
}
__device__ __forceinline__ void cpasync16(uint32_t dst, const void* src) {
    asm volatile("cp.async.cg.shared.global [%0], [%1], 16;" :: "r"(dst), "l"(src));
}

// group barrier: 64 arrivals on a group-private counter; gen monotone across replays
__device__ __forceinline__ void groupbar(int grp, unsigned gen) {
    __syncthreads();
    if (threadIdx.x == 0) {
        __threadfence();
        if (atomicAdd(&g_gcnt[grp*32], 1u) == (unsigned)(GBLK - 1)) {
            g_gcnt[grp*32] = 0;
            __threadfence();
            g_ggen[grp*32] = gen;
        } else {
            while ((int)(g_ggen[grp*32] - gen) < 0) { }
            __threadfence();
        }
    }
    __syncthreads();
}

// ------------------------- GEMM mainloop (64x128 tile, 8 warps) -------------------------
template<int KCHUNK>
__device__ __forceinline__ void gemm_core(
    const float* __restrict__ A, int lda,
    const __nv_bfloat16* __restrict__ Wt, int ldw,
    int n0, int row0, int kbeg, char* smem, float acc[2][4][4])
{
    uint32_t* Asw = (uint32_t*)smem;                 // [64][132] words
    uint32_t* Bsw = (uint32_t*)(smem + 33792);       // [2][128][BST] words
    const int SAW = 132;
    const int NKT = KCHUNK >> 4;
    constexpr int KC = (KCHUNK < 256) ? KCHUNK : 256;

    const int tid  = threadIdx.x;
    const int lane = tid & 31, warp = tid >> 5;
    const int wm = warp >> 2, wn = warp & 3;
    const int g = lane >> 2, t = lane & 3;
    const int bn = tid >> 1, bq = (tid & 1) << 3;
    const uint32_t bsm = (uint32_t)__cvta_generic_to_shared(Bsw);

    cpasync16(bsm + (uint32_t)((bn*BST + (bq>>1))*4),
              Wt + (size_t)(n0 + bn) * ldw + kbeg + bq);
    asm volatile("cp.async.commit_group;");

#pragma unroll
    for (int i = 0; i < 2; i++)
#pragma unroll
        for (int j = 0; j < 4; j++)
#pragma unroll
            for (int q = 0; q < 4; q++) acc[i][j][q] = 0.f;

#pragma unroll 1
    for (int ksg = 0; ksg < NKT; ksg++) {
        __syncthreads();
        if ((ksg & 15) == 0) {
            int kA = kbeg + ((ksg >> 4) << 8);
#pragma unroll
            for (int idx = tid * 4; idx < 64 * KC; idx += 1024) {
                int r = idx / KC, cc = idx % KC;
                float4 v = *(const float4*)(A + (size_t)(row0 + r) * lda + kA + cc);
                __nv_bfloat162 p0 = __float22bfloat162_rn(make_float2(v.x, v.y));
                __nv_bfloat162 p1 = __float22bfloat162_rn(make_float2(v.z, v.w));
                Asw[r * SAW + (cc >> 1)]     = *(uint32_t*)&p0;
                Asw[r * SAW + (cc >> 1) + 1] = *(uint32_t*)&p1;
            }
        }
        if (ksg + 1 < NKT)
            cpasync16(bsm + (uint32_t)(((((ksg+1)&1)*128*BST) + bn*BST + (bq>>1))*4),
                      Wt + (size_t)(n0 + bn) * ldw + kbeg + (ksg + 1) * 16 + bq);
        asm volatile("cp.async.commit_group;");
        asm volatile("cp.async.wait_group 1;");
        __syncthreads();

        const int wo = (ksg & 15) * 8;
        uint32_t a[2][4];
#pragma unroll
        for (int mt = 0; mt < 2; mt++) {
            const uint32_t* ap = Asw + (wm*32 + mt*16 + g) * SAW + wo + t;
            a[mt][0] = ap[0];
            a[mt][1] = ap[8 * SAW];
            a[mt][2] = ap[4];
            a[mt][3] = ap[8 * SAW + 4];
        }
        const uint32_t* bbase = Bsw + (ksg & 1) * 128 * BST;
        uint32_t bf[4][2];
#pragma unroll
        for (int nt = 0; nt < 4; nt++) {
            const uint32_t* bp = bbase + (wn*32 + nt*8 + g) * BST + t;
            bf[nt][0] = bp[0];
            bf[nt][1] = bp[4];
        }
#pragma unroll
        for (int mt = 0; mt < 2; mt++)
#pragma unroll
            for (int nt = 0; nt < 4; nt++)
                mma16816(acc[mt][nt], a[mt], bf[nt]);
    }
}

__device__ __forceinline__ void epi_partials(float acc[2][4][4], float* C, int N,
                                             int n0, int row0)
{
    const int lane = threadIdx.x & 31, warp = threadIdx.x >> 5;
    const int wm = warp >> 2, wn = warp & 3;
    const int g = lane >> 2, t = lane & 3;
#pragma unroll
    for (int mt = 0; mt < 2; mt++) {
        int m = row0 + wm*32 + mt*16 + g;
#pragma unroll
        for (int nt = 0; nt < 4; nt++) {
            int n = n0 + wn*32 + nt*8 + (t << 1);
            float* c = acc[mt][nt];
            *(float2*)(C + (size_t)m * N + n)       = make_float2(c[0], c[1]);
            *(float2*)(C + (size_t)(m + 8) * N + n) = make_float2(c[2], c[3]);
        }
    }
}

// ------------------------- fused preamble GEMMs: value + const (query@wct) -------------
__global__ __launch_bounds__(256, 2)
void gemms_pre(const float* __restrict__ enc, const float* __restrict__ valueb,
               const float* __restrict__ mask, const float* __restrict__ query)
{
    extern __shared__ char smem[];
    float acc[2][4][4];
    const int blk = blockIdx.x;
    if (blk < 480) {
        const int bx = blk & 1, by = blk >> 1;
        const int n0 = bx*128, row0 = by*64;
        gemm_core<256>(enc, 256, g_valuewt, 256, n0, row0, 0, smem, acc);
        const int lane = threadIdx.x & 31, warp = threadIdx.x >> 5;
        const int wm = warp >> 2, wn = warp & 3;
        const int g = lane >> 2, t = lane & 3;
#pragma unroll
        for (int mt = 0; mt < 2; mt++) {
#pragma unroll
            for (int mi = 0; mi < 2; mi++) {
                int m  = row0 + wm*32 + mt*16 + g + mi*8;
                int b  = m / TTn;
                int tt = m - b * TTn;
                float mk = mask[m];
#pragma unroll
                for (int nt = 0; nt < 4; nt++) {
                    int n = n0 + wn*32 + nt*8 + (t << 1);
                    int h = n >> 5, hd = n & 31;
                    float* c = acc[mt][nt];
                    float v0 = (c[mi*2]   + valueb[n])     * mk;
                    float v1 = (c[mi*2+1] + valueb[n + 1]) * mk;
                    *(float2*)(g_value + (((size_t)(b*HHn + h))*TTn + tt)*HDn + hd)
                        = make_float2(v0, v1);
                }
            }
        }
    } else {
        const int cb = blk - 480;                // 40 blocks: qgpc = query @ wct
        const int bx = cb % 10, by = cb / 10;
        gemm_core<256>(query, 256, g_wct, 256, bx*128, by*64, 0, smem, acc);
        epi_partials(acc, g_qgpc, 1280, bx*128, by*64);
    }
}

// ------------------------- streaming 128x128 GEMM core (logits) -------------------------
__device__ __forceinline__ void stream_core(const __nv_bfloat16* __restrict__ Ag0,
                                            const __nv_bfloat16* __restrict__ Bg0,
                                            char* smem, float acc[4][4][4])
{
    uint32_t* As = (uint32_t*)smem;
    uint32_t* Bs = (uint32_t*)(smem + 12288);
    const int tid = threadIdx.x;
    const int lane = tid & 31, warp = tid >> 5;
    const int wm = warp >> 2, wn = warp & 3;
    const int g = lane >> 2, t = lane & 3;
    const int lr = tid >> 1, lc = (tid & 1) << 3;
    const uint32_t asmb = (uint32_t)__cvta_generic_to_shared(As);
    const uint32_t bsmb = (uint32_t)__cvta_generic_to_shared(Bs);
    const uint32_t loff = (uint32_t)((lr*12 + (lc>>1))*4);
    const __nv_bfloat16* Ag = Ag0 + (size_t)lr*256 + lc;
    const __nv_bfloat16* Bg = Bg0 + (size_t)lr*256 + lc;

    cpasync16(asmb + loff, Ag);
    cpasync16(bsmb + loff, Bg);
    asm volatile("cp.async.commit_group;");

#pragma unroll
    for (int i = 0; i < 4; i++)
#pragma unroll
        for (int j = 0; j < 4; j++)
#pragma unroll
            for (int q = 0; q < 4; q++) acc[i][j][q] = 0.f;

#pragma unroll 1
    for (int ks = 0; ks < 16; ks++) {
        __syncthreads();
        if (ks + 1 < 16) {
            uint32_t bo = (uint32_t)(((ks + 1) & 1) * 6144);
            cpasync16(asmb + bo + loff, Ag + (ks + 1) * 16);
            cpasync16(bsmb + bo + loff, Bg + (ks + 1) * 16);
        }
        asm volatile("cp.async.commit_group;");
        asm volatile("cp.async.wait_group 1;");
        __syncthreads();

        const uint32_t* Ab = As + (ks & 1) * 1536;
        const uint32_t* Bb = Bs + (ks & 1) * 1536;
        uint32_t a[4][4];
#pragma unroll
        for (int mt = 0; mt < 4; mt++) {
            const uint32_t* ap = Ab + (wm*64 + mt*16 + g) * 12 + t;
            a[mt][0] = ap[0];
            a[mt][1] = ap[8 * 12];
            a[mt][2] = ap[4];
            a[mt][3] = ap[8 * 12 + 4];
        }
        uint32_t b[4][2];
#pragma unroll
        for (int nt = 0; nt < 4; nt++) {
            const uint32_t* bp = Bb + (wn*32 + nt*8 + g) * 12 + t;
            b[nt][0] = bp[0];
            b[nt][1] = bp[4];
        }
#pragma unroll
        for (int mt = 0; mt < 4; mt++)
#pragma unroll
            for (int nt = 0; nt < 4; nt++)
                mma16816(acc[mt][nt], a[mt], b[nt]);
    }
}

__global__ __launch_bounds__(256, 2)
void logits_stream1(const float* __restrict__ logitb)
{
    extern __shared__ char smem[];
    float acc[4][4][4];
    const int n0 = blockIdx.x * 128, row0 = blockIdx.y * 128;
    stream_core(g_hseqb + (size_t)row0*256, g_logitwt + (size_t)n0*256, smem, acc);

    const int tid = threadIdx.x;
    const int lane = tid & 31, warp = tid >> 5;
    const int wm = warp >> 2, wn = warp & 3;
    const int g = lane >> 2, t = lane & 3;

    float bias_r[4][2];
#pragma unroll
    for (int nt = 0; nt < 4; nt++) {
        int n = n0 + wn*32 + nt*8 + (t << 1);
        bias_r[nt][0] = (n     < VVn) ? logitb[n]     : 0.f;
        bias_r[nt][1] = (n + 1 < VVn) ? logitb[n + 1] : 0.f;
    }

    __syncthreads();
    float* s_ps = (float*)smem;
#pragma unroll
    for (int mt = 0; mt < 4; mt++) {
#pragma unroll
        for (int mi = 0; mi < 2; mi++) {
            int mloc = wm*64 + mt*16 + g + mi*8;
            float ls = 0.f;
#pragma unroll
            for (int nt = 0; nt < 4; nt++) {
                int n = n0 + wn*32 + nt*8 + (t << 1);
#pragma unroll
                for (int e = 0; e < 2; e++)
                    if (n + e < VVn)
                        ls += __expf(acc[mt][nt][mi*2 + e] + bias_r[nt][e]);
            }
            ls += __shfl_xor_sync(0xffffffffu, ls, 1);
            ls += __shfl_xor_sync(0xffffffffu, ls, 2);
            if (t == 0) s_ps[mloc*4 + wn] = ls;
        }
    }
    __syncthreads();
    if (tid < 128) {
        float ls = s_ps[tid*4] + s_ps[tid*4+1] + s_ps[tid*4+2] + s_ps[tid*4+3];
        g_lss[(size_t)(row0 + tid)*80 + blockIdx.x] = ls;
    }
}

__global__ __launch_bounds__(256)
void lse_reduce()
{
    const int w = threadIdx.x >> 5, lane = threadIdx.x & 31;
    const int m = blockIdx.x * 8 + w;
    float s = 0.f;
    const float* p = g_lss + (size_t)m * 80;
    if (lane < 79)       s  = p[lane];
    if (lane + 32 < 79)  s += p[lane + 32];
    if (lane + 64 < 79)  s += p[lane + 64];
#pragma unroll
    for (int o = 16; o; o >>= 1) s += __shfl_xor_sync(0xffffffffu, s, o);
    if (lane == 0) g_lse[m] = logf(s);
}

__global__ __launch_bounds__(256, 2)
void logits_stream2(const float* __restrict__ logitb, float* __restrict__ out)
{
    extern __shared__ char smem[];
    float acc[4][4][4];
    const int n0 = blockIdx.x * 128, row0 = blockIdx.y * 128;
    stream_core(g_hseqb + (size_t)row0*256, g_logitwt + (size_t)n0*256, smem, acc);

    const int lane = threadIdx.x & 31, warp = threadIdx.x >> 5;
    const int wm = warp >> 2, wn = warp & 3;
    const int g = lane >> 2, t = lane & 3;

#pragma unroll
    for (int mt = 0; mt < 4; mt++) {
#pragma unroll
        for (int mi = 0; mi < 2; mi++) {
            int m  = row0 + wm*64 + mt*16 + g + mi*8;
            int q  = m & 255, st = m >> 8;
            float lse = g_lse[m];
            float* orow = out + ((size_t)q * NSTEP + st) * VVn;
#pragma unroll
            for (int nt = 0; nt < 4; nt++) {
                int n = n0 + wn*32 + nt*8 + (t << 1);
                if (n < VVn) {
                    float* c = acc[mt][nt];
                    *(float2*)(orow + n) = make_float2(c[mi*2]   + logitb[n]   - lse,
                                                       c[mi*2+1] + logitb[n+1] - lse);
                }
            }
        }
    }
}

// ------------------------- preamble: all weight transposes -------------------------
__global__ __launch_bounds__(256)
void prep_transposes(const float* __restrict__ lw,
                     const float* __restrict__ wih, const float* __restrict__ whh,
                     const float* __restrict__ offw, const float* __restrict__ aww,
                     const float* __restrict__ hsw)
{
    __shared__ float s_t[64][65];
    const int blk = blockIdx.x;
    const int tx = threadIdx.x & 63, ty = threadIdx.x >> 6;

    if (blk < 632) {                                    // logitwt: 158 x 4
        const int n0 = (blk % 158) * 64, k0 = (blk / 158) * 64;
#pragma unroll
        for (int rr = ty; rr < 64; rr += 4)
            s_t[rr][tx] = (n0 + tx < VVn) ? lw[(size_t)(k0 + rr) * VVn + n0 + tx] : 0.f;
        __syncthreads();
#pragma unroll
        for (int rr = ty; rr < 64; rr += 4)
            g_logitwt[(size_t)(n0 + rr) * 256 + k0 + tx] = __float2bfloat16(s_t[tx][rr]);
    } else if (blk < 760) {                             // w21t: 16 n x 8 k tiles
        const int idx = blk - 632;
        const int n0 = (idx & 15) * 64, k0 = (idx >> 4) * 64;
#pragma unroll
        for (int rr = ty; rr < 64; rr += 4) {
            int k = k0 + rr, n = n0 + tx;
            int j = (n & 3) * 256 + (n >> 2);
            s_t[rr][tx] = (k < 256) ? wih[(size_t)(256 + k) * 1024 + j]
                                    : wih[(size_t)(k - 256) * 1024 + j];
        }
        __syncthreads();
#pragma unroll
        for (int rr = ty; rr < 64; rr += 4)
            g_w21t[(size_t)(n0 + rr) * 512 + k0 + tx] = __float2bfloat16(s_t[tx][rr]);
    } else if (blk < 856) {                             // bigw2t: 24 n x 4 k tiles
        const int idx = blk - 760;
        const int n0 = (idx % 24) * 64, k0 = (idx / 24) * 64;
#pragma unroll
        for (int rr = ty; rr < 64; rr += 4) {
            int k = k0 + rr, n = n0 + tx;
            float v;
            if (n < 128)      v = offw[k*128 + n];
            else if (n < 256) v = aww[k*128 + (n - 128)];
            else if (n < 512) v = hsw[k*256 + (n - 256)];
            else {
                int m = n - 512;
                v = whh[(size_t)k * 1024 + (m & 3) * 256 + (m >> 2)];
            }
            s_t[rr][tx] = v;
        }
        __syncthreads();
#pragma unroll
        for (int rr = ty; rr < 64; rr += 4)
            g_bigw2t[(size_t)(n0 + rr) * 256 + k0 + tx] = __float2bfloat16(s_t[tx][rr]);
    } else {                                            // wct: 20 n x 4 k tiles
        const int idx = blk - 856;
        const int n0 = (idx % 20) * 64, k0 = (idx / 20) * 64;
#pragma unroll
        for (int rr = ty; rr < 64; rr += 4) {
            int k = k0 + rr, n = n0 + tx;
            float v;
            if (n < 1024)
                v = wih[(size_t)(512 + k) * 1024 + (n & 3) * 256 + (n >> 2)];
            else {
                int m = n - 1024;
                v = (m < 128) ? offw[(256 + k)*128 + m] : aww[(256 + k)*128 + (m - 128)];
            }
            s_t[rr][tx] = v;
        }
        __syncthreads();
#pragma unroll
        for (int rr = ty; rr < 64; rr += 4)
            g_wct[(size_t)(n0 + rr) * 256 + k0 + tx] = __float2bfloat16(s_t[tx][rr]);
    }
}

__global__ __launch_bounds__(256)
void build_small(const float* __restrict__ ctxw, const float* __restrict__ valuew,
                 const float* __restrict__ hsb,  const float* __restrict__ ctxb)
{
    const int blk = blockIdx.x, tid = threadIdx.x;
    if (blk < 256) {
        int q = blk;
        g_h[q*256 + tid] = 0.f;
        g_c[q*256 + tid] = 0.f;
        if (q == 0) g_hsbc[tid] = hsb[tid] + ctxb[tid];
    } else {
        int i = (blk - 256) * 256 + tid;                // 0..65535
        if (i < 256*32) {
            int n = i >> 5, k = i & 31;
            g_ctxwt[n*32 + k] = __float2bfloat16(ctxw[k*256 + n]);
        }
        int n = i >> 8, k = i & 255;
        g_valuewt[n*256 + k] = __float2bfloat16(valuew[k*256 + n]);
    }
}

// ------------------------- fused MSDA (one query per block; persistent ctx) -------------
__device__ void msda_one(int n, int step,
                         const float* __restrict__ rp,   const float* __restrict__ vr,
                         const int*   __restrict__ seq,  const float* __restrict__ embw,
                         const float* __restrict__ offb, const float* __restrict__ awb,
                         const float* __restrict__ alphab, char* smem)
{
    uint32_t* s_hsampb = (uint32_t*)smem;              // [128][17]
    float* s_hb    = (float*)(smem + 8704);
    float* s_off   = (float*)(smem + 9728);
    float* s_aw    = (float*)(smem + 10240);
    float* s_alpha = (float*)(smem + 10752);
    float* s_wgt   = (float*)(smem + 11264);
    const uint32_t* s_ctx = (const uint32_t*)(smem + CTXOFF);
    const float*    s_aww = (const float*)(smem + AWOFF);

    const int b    = n >> 5;
    const int tid  = threadIdx.x;
    const int lane = tid & 31;
    const int w    = tid >> 5;

    __syncthreads();

    {
        int tok = (step == 0) ? 1 : seq[n*SSq + step - 1];
        g_ae[n*512 + 256 + tid] = embw[(size_t)tok * DDim + tid];
        float s = 0.f;
#pragma unroll
        for (int zu = 0; zu < 4; zu++)
            s += g_U[((size_t)zu*NEq + n)*1536 + 256 + tid];
        s_hb[tid] = s + g_hsbc[tid];
    }
    if (tid < 128) {
        float so = 0.f, sa = 0.f;
#pragma unroll
        for (int zu = 0; zu < 4; zu++) {
            so += g_U[((size_t)zu*NEq + n)*1536 + tid];
            sa += g_U[((size_t)zu*NEq + n)*1536 + 128 + tid];
        }
        so += g_qgpc[n*1280 + 1024 + tid] + offb[tid];
        sa += g_qgpc[n*1280 + 1152 + tid] + awb[tid];
        s_off[tid] = so;
        float m = sa;
#pragma unroll
        for (int o = 8; o; o >>= 1) m = fmaxf(m, __shfl_xor_sync(0xffffffffu, m, o));
        float e = __expf(sa - m);
        float sm = e;
#pragma unroll
        for (int o = 8; o; o >>= 1) sm += __shfl_xor_sync(0xffffffffu, sm, o);
        s_aw[tid] = e / sm;
    }
    __syncthreads();

    {
        const float rpn = rp[n];
        __nv_bfloat16* hs = (__nv_bfloat16*)s_hsampb;
#pragma unroll
        for (int i = 0; i < 16; i++) {
            int r = (w << 4) + i;
            int h = r >> 4;
            int l = (r >> 2) & 3;
            int shape_l = 1024 >> l;
            int start_l = 2048 - (2048 >> l);
            float refl = rpn * vr[b*4 + l];
            float x = refl * (float)shape_l + s_off[r] - 0.5f;
            float x0f = floorf(x);
            float wf = x - x0f;
            int x0 = (int)x0f;
            const float* vbase = g_value + (((size_t)(b*HHn + h))*TTn + start_l) * HDn;
            float g0 = (x0 >= 0     && x0     < shape_l) ? vbase[(size_t)x0     * HDn + lane] : 0.f;
            float g1 = (x0 + 1 >= 0 && x0 + 1 < shape_l) ? vbase[(size_t)(x0+1) * HDn + lane] : 0.f;
            hs[r*34 + lane] = __float2bfloat16((g0 * (1.f - wf) + g1 * wf) * s_aw[r]);
        }
    }
    __syncthreads();

    {
        const int g = lane >> 2, t = lane & 3;
        const int r0 = w << 4;
        const float ab = alphab[0];

        uint32_t a[2][4];
#pragma unroll
        for (int ks = 0; ks < 2; ks++) {
            const uint32_t* ap = s_hsampb + (r0 + g) * 17 + ks*8 + t;
            a[ks][0] = ap[0];
            a[ks][1] = ap[8 * 17];
            a[ks][2] = ap[4];
            a[ks][3] = ap[8 * 17 + 4];
        }
        float p0 = 0.f, p1 = 0.f;
#pragma unroll
        for (int nb = 0; nb < 256; nb += 8) {
            float c[4] = {0.f, 0.f, 0.f, 0.f};
#pragma unroll
            for (int ks = 0; ks < 2; ks++) {
                const uint32_t* bp = s_ctx + (nb + g) * 17 + ks*8 + t;
                uint32_t bf2[2] = { bp[0], bp[4] };
                mma16816(c, a[ks], bf2);
            }
            int col = nb + (t << 1);
            float hb0 = s_hb[col], hb1 = s_hb[col + 1];
            float aw0 = s_aww[col], aw1 = s_aww[col + 1];
            p0 = fmaf(tanha(c[0] + hb0), aw0, fmaf(tanha(c[1] + hb1), aw1, p0));
            p1 = fmaf(tanha(c[2] + hb0), aw0, fmaf(tanha(c[3] + hb1), aw1, p1));
        }
        p0 += __shfl_xor_sync(0xffffffffu, p0, 1);
        p0 += __shfl_xor_sync(0xffffffffu, p0, 2);
        p1 += __shfl_xor_sync(0xffffffffu, p1, 1);
        p1 += __shfl_xor_sync(0xffffffffu, p1, 2);
        if (t == 0) {
            s_alpha[r0 + g]     = p0 + ab;
            s_alpha[r0 + g + 8] = p1 + ab;
        }
    }
    __syncthreads();

    if (tid < 128) {
        float v = s_alpha[tid];
        float m = v;
#pragma unroll
        for (int o = 8; o; o >>= 1) m = fmaxf(m, __shfl_xor_sync(0xffffffffu, m, o));
        float e = __expf(v - m);
        float sm = e;
#pragma unroll
        for (int o = 8; o; o >>= 1) sm += __shfl_xor_sync(0xffffffffu, sm, o);
        s_wgt[tid] = e / sm;
    }
    __syncthreads();

    {
        int h = tid >> 5, hd = tid & 31;
        const __nv_bfloat16* hs = (const __nv_bfloat16*)s_hsampb;
        float res = 0.f;
#pragma unroll
        for (int lp = 0; lp < 16; lp++)
            res = fmaf(s_wgt[(h << 4) + lp],
                       __bfloat162float(hs[((h << 4) + lp)*34 + hd]), res);
        g_ae[n*512 + tid] = res;
    }
}

// ------------------------- persistent recurrent loop (4 group-local barriers/step) -------
__global__ __launch_bounds__(256, 2)
void loop_kernel(const float* __restrict__ rp,   const float* __restrict__ vr,
                 const int*   __restrict__ seq,  const float* __restrict__ embw,
                 const float* __restrict__ offb, const float* __restrict__ awb,
                 const float* __restrict__ alphaw, const float* __restrict__ alphab)
{
    extern __shared__ char smem[];
    const int blk   = blockIdx.x;
    const int grp   = blk >> 6;          // 4 independent groups of 64 blocks
    const int local = blk & 63;
    const int qbase = grp << 6;          // 64 queries per group
    const int tid   = threadIdx.x;
    unsigned bgen = g_ggen[grp*32];      // group-private generation (monotone across replays)

    // load persistent ctx + alphaw once
    {
        uint32_t* s_ctx = (uint32_t*)(smem + CTXOFF);
        const uint32_t* cg = (const uint32_t*)g_ctxwt;
        for (int i = tid; i < 256*16; i += 256)
            s_ctx[(i >> 4)*17 + (i & 15)] = cg[i];
        ((float*)(smem + AWOFF))[tid] = alphaw[tid];
    }

    for (int it = 0; it <= NSTEP; it++) {
        if (it > 0) {
            // ---- P0: LSTM (one query per block) ----
            {
                int q = qbase + local, d = tid;
                float4 s = make_float4(0.f, 0.f, 0.f, 0.f);
#pragma unroll
                for (int z = 0; z < 8; z++) {
                    float4 gp = *(const float4*)&g_gatesp[((size_t)z*NEq + q)*1024 + d*4];
                    s.x += gp.x; s.y += gp.y; s.z += gp.z; s.w += gp.w;
                }
#pragma unroll
                for (int zu = 0; zu < 4; zu++) {
                    float4 uv = *(const float4*)&g_U[((size_t)zu*NEq + q)*1536 + 512 + d*4];
                    s.x += uv.x; s.y += uv.y; s.z += uv.z; s.w += uv.w;
                }
                float4 qv = *(const float4*)&g_qgpc[q*1280 + d*4];
                float gi = s.x + qv.x, gf = s.y + qv.y, gg = s.z + qv.z, go = s.w + qv.w;
                float c  = g_c[q*256 + d];
                float si = 1.f / (1.f + expf(-gi));
                float sf = 1.f / (1.f + expf(-gf));
                float so = 1.f / (1.f + expf(-go));
                float c2 = sf * c + si * tanhf(gg);
                float h2 = so * tanhf(c2);
                g_c[q*256 + d] = c2;
                g_h[q*256 + d] = h2;
                g_hseqb[((size_t)(it-1)*NEq + q)*DDim + d] = __float2bfloat16(h2);
            }
            if (it == NSTEP) break;
            groupbar(grp, ++bgen);
        }

        // ---- P1: U_g = h_g @ bigw2t (64x1536, K=256) split-K4 -> 48 blocks x 4 iters ----
        if (local < 48) {
            int bz = local / 12, bx = local % 12;
            float acc[2][4][4];
            gemm_core<64>(g_h + qbase*256, 256, g_bigw2t, 256, bx*128, 0, bz*64, smem, acc);
            epi_partials(acc, g_U + (size_t)bz*NEq*1536 + (size_t)qbase*1536, 1536, bx*128, 0);
        }
        groupbar(grp, ++bgen);

        // ---- P2: MSDA, 1 query per block ----
        msda_one(qbase + local, it, rp, vr, seq, embw, offb, awb, alphab, smem);
        groupbar(grp, ++bgen);

        // ---- P3: gates_part = ae_g @ w21t (64x1024, K=512) split-K8 -> 64 blocks x 4 iters
        {
            int bz = local >> 3, bx = local & 7;
            float acc[2][4][4];
            gemm_core<64>(g_ae + qbase*512, 512, g_w21t, 512, bx*128, 0, bz*64, smem, acc);
            epi_partials(acc, g_gatesp + (size_t)bz*NEq*1024 + (size_t)qbase*1024, 1024, bx*128, 0);
        }
        groupbar(grp, ++bgen);
    }
}

// ------------------------- launch -------------------------
extern "C" void kernel_launch(void* const* d_in, const int* in_sizes, int n_in,
                              void* d_out, int out_size)
{
    const int*   seq    = (const int*)  d_in[0];
    const float* query  = (const float*)d_in[1];
    const float* rp     = (const float*)d_in[2];
    const float* enc    = (const float*)d_in[3];
    const float* mask   = (const float*)d_in[4];
    const float* vrr    = (const float*)d_in[5];
    const float* embw   = (const float*)d_in[6];
    const float* logitw = (const float*)d_in[7];
    const float* logitb = (const float*)d_in[8];
    const float* valuew = (const float*)d_in[9];
    const float* valueb = (const float*)d_in[10];
    const float* offw   = (const float*)d_in[11];
    const float* offb   = (const float*)d_in[12];
    const float* aww    = (const float*)d_in[13];
    const float* awb    = (const float*)d_in[14];
    const float* ctxw   = (const float*)d_in[15];
    const float* ctxb   = (const float*)d_in[16];
    const float* hsw    = (const float*)d_in[17];
    const float* hsb    = (const float*)d_in[18];
    const float* alphaw = (const float*)d_in[19];
    const float* alphab = (const float*)d_in[20];
    const float* wih    = (const float*)d_in[21];
    const float* whh    = (const float*)d_in[22];
    float* out = (float*)d_out;

    cudaFuncSetAttribute(gemms_pre,      cudaFuncAttributeMaxDynamicSharedMemorySize, SMEMSZ);
    cudaFuncSetAttribute(loop_kernel,    cudaFuncAttributeMaxDynamicSharedMemorySize, SMEMLOOP);
    cudaFuncSetAttribute(logits_stream1, cudaFuncAttributeMaxDynamicSharedMemorySize, SMEMS2);
    cudaFuncSetAttribute(logits_stream2, cudaFuncAttributeMaxDynamicSharedMemorySize, SMEMS2);

    // idx 0..2 preamble; idx 3 = loop_kernel (ncu displays idx 3)
    prep_transposes<<<936, 256>>>(logitw, wih, whh, offw, aww, hsw);
    build_small    <<<512, 256>>>(ctxw, valuew, hsb, ctxb);
    gemms_pre      <<<520, 256, SMEMSZ>>>(enc, valueb, mask, query);

    loop_kernel<<<LOOPBLK, 256, SMEMLOOP>>>(rp, vrr, seq, embw, offb, awb, alphaw, alphab);

    logits_stream1<<<dim3(79, 40), 256, SMEMS2>>>(logitb);
    lse_reduce    <<<MTOT/8, 256>>>();
    logits_stream2<<<dim3(79, 40), 256, SMEMS2>>>(logitb, out);
}

// round 13
// speedup vs baseline: 1.3274x; 1.0424x over previous
#include <cuda_runtime.h>
#include <cuda_bf16.h>
#include <math.h>
#include <stdint.h>

#define NB    8
#define NEq   256
#define SSq   21
#define NSTEP 20
#define DDim  256
#define HHn   8
#define HDn   32
#define VVn   10000
#define TTn   1920
#define VPAD  10112
#define MTOT  (NSTEP*NEq)   // 5120
#define LOOPBLK 256
#define NGRP  4
#define GBLK  64
#define BST   12
#define SMEMSZ  (33792 + 2*128*BST*4)   // 46080 (preamble GEMM scratch)
#define CTXOFF  46080
#define AWOFF   (CTXOFF + 17408)        // 63488 alphaw (1024B)
#define OBOFF   (AWOFF + 1024)          // 64512 offb (512B)
#define ABOFF   (OBOFF + 512)           // 65024 awb (512B)
#define HBOFF   (ABOFF + 512)           // 65536 hsbc (1024B)
#define SMEMLOOP (HBOFF + 1024)         // 66560
#define SMEMS2  (2*128*12*4*2)          // 24576

// ------------------------- device scratch -------------------------
__device__ __align__(16) float g_value [NB*HHn*TTn*HDn];
__device__ __align__(16) float g_U     [4*NEq*1536];  // split-K4 partials
__device__ __align__(16) float g_gatesp[8*NEq*1024];  // split-K8 partials
__device__ __align__(16) float g_ae    [NEq*256];     // attn only
__device__ __align__(16) float g_embseq[MTOT*256];    // emb rows per (step,query)
__device__ __align__(16) float g_qgpc  [NEq*1280];
__device__ __align__(16) float g_h     [NEq*DDim];
__device__ __align__(16) float g_hsbc  [256];
__device__ __align__(16) float g_lss   [MTOT*80];
__device__ __align__(16) float g_lse   [MTOT];
__device__ __align__(16) __nv_bfloat16 g_hseqb  [MTOT*DDim];
__device__ __align__(16) __nv_bfloat16 g_bigw2t [1536*256];
__device__ __align__(16) __nv_bfloat16 g_w21t   [1024*512];
__device__ __align__(16) __nv_bfloat16 g_wct    [1280*256];
__device__ __align__(16) __nv_bfloat16 g_logitwt[VPAD*256];
__device__ __align__(16) __nv_bfloat16 g_ctxwt  [256*32];
__device__ __align__(16) __nv_bfloat16 g_valuewt[256*256];

// per-group barrier state (distinct 128B lines)
__device__ unsigned g_gcnt[NGRP*32];
__device__ volatile unsigned g_ggen[NGRP*32];

// ------------------------- helpers -------------------------
__device__ __forceinline__ float tanha(float x) {
    float y; asm("tanh.approx.f32 %0, %1;" : "=f"(y) : "f"(x)); return y;
}
__device__ __forceinline__ void mma16816(float* c, const uint32_t* a, const uint32_t* b) {
    asm volatile(
        "mma.sync.aligned.m16n8k16.row.col.f32.bf16.bf16.f32 "
        "{%0,%1,%2,%3}, {%4,%5,%6,%7}, {%8,%9}, {%0,%1,%2,%3};"
        : "+f"(c[0]), "+f"(c[1]), "+f"(c[2]), "+f"(c[3])
        : "r"(a[0]), "r"(a[1]), "r"(a[2]), "r"(a[3]), "r"(b[0]), "r"(b[1]));
}
__device__ __forceinline__ void cpasync16(uint32_t dst, const void* src) {
    asm volatile("cp.async.cg.shared.global [%0], [%1], 16;" :: "r"(dst), "l"(src));
}

__device__ __forceinline__ void groupbar(int grp, unsigned gen) {
    __syncthreads();
    if (threadIdx.x == 0) {
        __threadfence();
        if (atomicAdd(&g_gcnt[grp*32], 1u) == (unsigned)(GBLK - 1)) {
            g_gcnt[grp*32] = 0;
            __threadfence();
            g_ggen[grp*32] = gen;
        } else {
            while ((int)(g_ggen[grp*32] - gen) < 0) { }
            __threadfence();
        }
    }
    __syncthreads();
}

// ------------------------- single-shot GEMM core (64x128 tile, K=64, 1 sync) -------------
__device__ __forceinline__ void gemm1shot(
    const float* __restrict__ A, int lda,                 // A: 64 x 64 fp32 (pre-offset)
    const __nv_bfloat16* __restrict__ Wt, int ldw,
    int n0, int kbegW, char* smem, float acc[2][4][4])
{
    uint32_t* Asw = (uint32_t*)smem;            // [64][36] words
    uint32_t* Bsw = (uint32_t*)(smem + 9216);   // [128][36] words
    const int tid = threadIdx.x;
    const int lane = tid & 31, warp = tid >> 5;
    const int wm = warp >> 2, wn = warp & 3;
    const int g = lane >> 2, t = lane & 3;

    // B (128x64 bf16) via cp.async
    {
        const int br = tid >> 1;
        const int bo = (tid & 1) << 4;          // word offset: 0 or 16
        const uint32_t bsm = (uint32_t)__cvta_generic_to_shared(Bsw);
        const __nv_bfloat16* src = Wt + (size_t)(n0 + br) * ldw + kbegW + (bo << 1);
#pragma unroll
        for (int j = 0; j < 4; j++)
            cpasync16(bsm + (uint32_t)((br*36 + bo + j*4)*4), src + j*8);
        asm volatile("cp.async.commit_group;");
    }
    // A (64x64 fp32 -> bf16)
    {
        const int ar = tid >> 2;
        const int ac = (tid & 3) << 4;
        const float* ap = A + (size_t)ar * lda + ac;
        uint32_t* dst = Asw + ar*36 + (ac >> 1);
#pragma unroll
        for (int j = 0; j < 4; j++) {
            float4 v = *(const float4*)(ap + j*4);
            __nv_bfloat162 p0 = __float22bfloat162_rn(make_float2(v.x, v.y));
            __nv_bfloat162 p1 = __float22bfloat162_rn(make_float2(v.z, v.w));
            dst[j*2]     = *(uint32_t*)&p0;
            dst[j*2 + 1] = *(uint32_t*)&p1;
        }
    }
    asm volatile("cp.async.wait_group 0;");
    __syncthreads();

#pragma unroll
    for (int i = 0; i < 2; i++)
#pragma unroll
        for (int j = 0; j < 4; j++)
#pragma unroll
            for (int q = 0; q < 4; q++) acc[i][j][q] = 0.f;

#pragma unroll
    for (int ks = 0; ks < 4; ks++) {
        const int wo = ks * 8;
        uint32_t a[2][4];
#pragma unroll
        for (int mt = 0; mt < 2; mt++) {
            const uint32_t* ap = Asw + (wm*32 + mt*16 + g) * 36 + wo + t;
            a[mt][0] = ap[0];
            a[mt][1] = ap[8 * 36];
            a[mt][2] = ap[4];
            a[mt][3] = ap[8 * 36 + 4];
        }
        uint32_t bf[4][2];
#pragma unroll
        for (int nt = 0; nt < 4; nt++) {
            const uint32_t* bp = Bsw + (wn*32 + nt*8 + g) * 36 + wo + t;
            bf[nt][0] = bp[0];
            bf[nt][1] = bp[4];
        }
#pragma unroll
        for (int mt = 0; mt < 2; mt++)
#pragma unroll
            for (int nt = 0; nt < 4; nt++)
                mma16816(acc[mt][nt], a[mt], bf[nt]);
    }
}

__device__ __forceinline__ void epi_partials(float acc[2][4][4], float* C, int N,
                                             int n0, int row0)
{
    const int lane = threadIdx.x & 31, warp = threadIdx.x >> 5;
    const int wm = warp >> 2, wn = warp & 3;
    const int g = lane >> 2, t = lane & 3;
#pragma unroll
    for (int mt = 0; mt < 2; mt++) {
        int m = row0 + wm*32 + mt*16 + g;
#pragma unroll
        for (int nt = 0; nt < 4; nt++) {
            int n = n0 + wn*32 + nt*8 + (t << 1);
            float* c = acc[mt][nt];
            *(float2*)(C + (size_t)m * N + n)       = make_float2(c[0], c[1]);
            *(float2*)(C + (size_t)(m + 8) * N + n) = make_float2(c[2], c[3]);
        }
    }
}

// ------------------------- multi-chunk GEMM core (preamble only) -------------------------
template<int KCHUNK>
__device__ __forceinline__ void gemm_core(
    const float* __restrict__ A, int lda,
    const __nv_bfloat16* __restrict__ Wt, int ldw,
    int n0, int row0, int kbeg, char* smem, float acc[2][4][4])
{
    uint32_t* Asw = (uint32_t*)smem;                 // [64][132] words
    uint32_t* Bsw = (uint32_t*)(smem + 33792);       // [2][128][BST] words
    const int SAW = 132;
    const int NKT = KCHUNK >> 4;
    constexpr int KC = (KCHUNK < 256) ? KCHUNK : 256;

    const int tid  = threadIdx.x;
    const int lane = tid & 31, warp = tid >> 5;
    const int wm = warp >> 2, wn = warp & 3;
    const int g = lane >> 2, t = lane & 3;
    const int bn = tid >> 1, bq = (tid & 1) << 3;
    const uint32_t bsm = (uint32_t)__cvta_generic_to_shared(Bsw);

    cpasync16(bsm + (uint32_t)((bn*BST + (bq>>1))*4),
              Wt + (size_t)(n0 + bn) * ldw + kbeg + bq);
    asm volatile("cp.async.commit_group;");

#pragma unroll
    for (int i = 0; i < 2; i++)
#pragma unroll
        for (int j = 0; j < 4; j++)
#pragma unroll
            for (int q = 0; q < 4; q++) acc[i][j][q] = 0.f;

#pragma unroll 1
    for (int ksg = 0; ksg < NKT; ksg++) {
        __syncthreads();
        if ((ksg & 15) == 0) {
            int kA = kbeg + ((ksg >> 4) << 8);
#pragma unroll
            for (int idx = tid * 4; idx < 64 * KC; idx += 1024) {
                int r = idx / KC, cc = idx % KC;
                float4 v = *(const float4*)(A + (size_t)(row0 + r) * lda + kA + cc);
                __nv_bfloat162 p0 = __float22bfloat162_rn(make_float2(v.x, v.y));
                __nv_bfloat162 p1 = __float22bfloat162_rn(make_float2(v.z, v.w));
                Asw[r * SAW + (cc >> 1)]     = *(uint32_t*)&p0;
                Asw[r * SAW + (cc >> 1) + 1] = *(uint32_t*)&p1;
            }
        }
        if (ksg + 1 < NKT)
            cpasync16(bsm + (uint32_t)(((((ksg+1)&1)*128*BST) + bn*BST + (bq>>1))*4),
                      Wt + (size_t)(n0 + bn) * ldw + kbeg + (ksg + 1) * 16 + bq);
        asm volatile("cp.async.commit_group;");
        asm volatile("cp.async.wait_group 1;");
        __syncthreads();

        const int wo = (ksg & 15) * 8;
        uint32_t a[2][4];
#pragma unroll
        for (int mt = 0; mt < 2; mt++) {
            const uint32_t* ap = Asw + (wm*32 + mt*16 + g) * SAW + wo + t;
            a[mt][0] = ap[0];
            a[mt][1] = ap[8 * SAW];
            a[mt][2] = ap[4];
            a[mt][3] = ap[8 * SAW + 4];
        }
        const uint32_t* bbase = Bsw + (ksg & 1) * 128 * BST;
        uint32_t bf[4][2];
#pragma unroll
        for (int nt = 0; nt < 4; nt++) {
            const uint32_t* bp = bbase + (wn*32 + nt*8 + g) * BST + t;
            bf[nt][0] = bp[0];
            bf[nt][1] = bp[4];
        }
#pragma unroll
        for (int mt = 0; mt < 2; mt++)
#pragma unroll
            for (int nt = 0; nt < 4; nt++)
                mma16816(acc[mt][nt], a[mt], bf[nt]);
    }
}

// ------------------------- fused preamble GEMMs: value + const (query@wct) -------------
__global__ __launch_bounds__(256, 2)
void gemms_pre(const float* __restrict__ enc, const float* __restrict__ valueb,
               const float* __restrict__ mask, const float* __restrict__ query)
{
    extern __shared__ char smem[];
    float acc[2][4][4];
    const int blk = blockIdx.x;
    if (blk < 480) {
        const int bx = blk & 1, by = blk >> 1;
        const int n0 = bx*128, row0 = by*64;
        gemm_core<256>(enc, 256, g_valuewt, 256, n0, row0, 0, smem, acc);
        const int lane = threadIdx.x & 31, warp = threadIdx.x >> 5;
        const int wm = warp >> 2, wn = warp & 3;
        const int g = lane >> 2, t = lane & 3;
#pragma unroll
        for (int mt = 0; mt < 2; mt++) {
#pragma unroll
            for (int mi = 0; mi < 2; mi++) {
                int m  = row0 + wm*32 + mt*16 + g + mi*8;
                int b  = m / TTn;
                int tt = m - b * TTn;
                float mk = mask[m];
#pragma unroll
                for (int nt = 0; nt < 4; nt++) {
                    int n = n0 + wn*32 + nt*8 + (t << 1);
                    int h = n >> 5, hd = n & 31;
                    float* c = acc[mt][nt];
                    float v0 = (c[mi*2]   + valueb[n])     * mk;
                    float v1 = (c[mi*2+1] + valueb[n + 1]) * mk;
                    *(float2*)(g_value + (((size_t)(b*HHn + h))*TTn + tt)*HDn + hd)
                        = make_float2(v0, v1);
                }
            }
        }
    } else {
        const int cb = blk - 480;
        const int bx = cb % 10, by = cb / 10;
        gemm_core<256>(query, 256, g_wct, 256, bx*128, by*64, 0, smem, acc);
        epi_partials(acc, g_qgpc + (size_t)(by*64)*1280, 1280, bx*128, 0);
    }
}

// ------------------------- streaming 128x128 GEMM core (logits) -------------------------
__device__ __forceinline__ void stream_core(const __nv_bfloat16* __restrict__ Ag0,
                                            const __nv_bfloat16* __restrict__ Bg0,
                                            char* smem, float acc[4][4][4])
{
    uint32_t* As = (uint32_t*)smem;
    uint32_t* Bs = (uint32_t*)(smem + 12288);
    const int tid = threadIdx.x;
    const int lane = tid & 31, warp = tid >> 5;
    const int wm = warp >> 2, wn = warp & 3;
    const int g = lane >> 2, t = lane & 3;
    const int lr = tid >> 1, lc = (tid & 1) << 3;
    const uint32_t asmb = (uint32_t)__cvta_generic_to_shared(As);
    const uint32_t bsmb = (uint32_t)__cvta_generic_to_shared(Bs);
    const uint32_t loff = (uint32_t)((lr*12 + (lc>>1))*4);
    const __nv_bfloat16* Ag = Ag0 + (size_t)lr*256 + lc;
    const __nv_bfloat16* Bg = Bg0 + (size_t)lr*256 + lc;

    cpasync16(asmb + loff, Ag);
    cpasync16(bsmb + loff, Bg);
    asm volatile("cp.async.commit_group;");

#pragma unroll
    for (int i = 0; i < 4; i++)
#pragma unroll
        for (int j = 0; j < 4; j++)
#pragma unroll
            for (int q = 0; q < 4; q++) acc[i][j][q] = 0.f;

#pragma unroll 1
    for (int ks = 0; ks < 16; ks++) {
        __syncthreads();
        if (ks + 1 < 16) {
            uint32_t bo = (uint32_t)(((ks + 1) & 1) * 6144);
            cpasync16(asmb + bo + loff, Ag + (ks + 1) * 16);
            cpasync16(bsmb + bo + loff, Bg + (ks + 1) * 16);
        }
        asm volatile("cp.async.commit_group;");
        asm volatile("cp.async.wait_group 1;");
        __syncthreads();

        const uint32_t* Ab = As + (ks & 1) * 1536;
        const uint32_t* Bb = Bs + (ks & 1) * 1536;
        uint32_t a[4][4];
#pragma unroll
        for (int mt = 0; mt < 4; mt++) {
            const uint32_t* ap = Ab + (wm*64 + mt*16 + g) * 12 + t;
            a[mt][0] = ap[0];
            a[mt][1] = ap[8 * 12];
            a[mt][2] = ap[4];
            a[mt][3] = ap[8 * 12 + 4];
        }
        uint32_t b[4][2];
#pragma unroll
        for (int nt = 0; nt < 4; nt++) {
            const uint32_t* bp = Bb + (wn*32 + nt*8 + g) * 12 + t;
            b[nt][0] = bp[0];
            b[nt][1] = bp[4];
        }
#pragma unroll
        for (int mt = 0; mt < 4; mt++)
#pragma unroll
            for (int nt = 0; nt < 4; nt++)
                mma16816(acc[mt][nt], a[mt], b[nt]);
    }
}

__global__ __launch_bounds__(256, 2)
void logits_stream1(const float* __restrict__ logitb)
{
    extern __shared__ char smem[];
    float acc[4][4][4];
    const int n0 = blockIdx.x * 128, row0 = blockIdx.y * 128;
    stream_core(g_hseqb + (size_t)row0*256, g_logitwt + (size_t)n0*256, smem, acc);

    const int tid = threadIdx.x;
    const int lane = tid & 31, warp = tid >> 5;
    const int wm = warp >> 2, wn = warp & 3;
    const int g = lane >> 2, t = lane & 3;

    float bias_r[4][2];
#pragma unroll
    for (int nt = 0; nt < 4; nt++) {
        int n = n0 + wn*32 + nt*8 + (t << 1);
        bias_r[nt][0] = (n     < VVn) ? logitb[n]     : 0.f;
        bias_r[nt][1] = (n + 1 < VVn) ? logitb[n + 1] : 0.f;
    }

    __syncthreads();
    float* s_ps = (float*)smem;
#pragma unroll
    for (int mt = 0; mt < 4; mt++) {
#pragma unroll
        for (int mi = 0; mi < 2; mi++) {
            int mloc = wm*64 + mt*16 + g + mi*8;
            float ls = 0.f;
#pragma unroll
            for (int nt = 0; nt < 4; nt++) {
                int n = n0 + wn*32 + nt*8 + (t << 1);
#pragma unroll
                for (int e = 0; e < 2; e++)
                    if (n + e < VVn)
                        ls += __expf(acc[mt][nt][mi*2 + e] + bias_r[nt][e]);
            }
            ls += __shfl_xor_sync(0xffffffffu, ls, 1);
            ls += __shfl_xor_sync(0xffffffffu, ls, 2);
            if (t == 0) s_ps[mloc*4 + wn] = ls;
        }
    }
    __syncthreads();
    if (tid < 128) {
        float ls = s_ps[tid*4] + s_ps[tid*4+1] + s_ps[tid*4+2] + s_ps[tid*4+3];
        g_lss[(size_t)(row0 + tid)*80 + blockIdx.x] = ls;
    }
}

__global__ __launch_bounds__(256)
void lse_reduce()
{
    const int w = threadIdx.x >> 5, lane = threadIdx.x & 31;
    const int m = blockIdx.x * 8 + w;
    float s = 0.f;
    const float* p = g_lss + (size_t)m * 80;
    if (lane < 79)       s  = p[lane];
    if (lane + 32 < 79)  s += p[lane + 32];
    if (lane + 64 < 79)  s += p[lane + 64];
#pragma unroll
    for (int o = 16; o; o >>= 1) s += __shfl_xor_sync(0xffffffffu, s, o);
    if (lane == 0) g_lse[m] = logf(s);
}

__global__ __launch_bounds__(256, 2)
void logits_stream2(const float* __restrict__ logitb, float* __restrict__ out)
{
    extern __shared__ char smem[];
    float acc[4][4][4];
    const int n0 = blockIdx.x * 128, row0 = blockIdx.y * 128;
    stream_core(g_hseqb + (size_t)row0*256, g_logitwt + (size_t)n0*256, smem, acc);

    const int lane = threadIdx.x & 31, warp = threadIdx.x >> 5;
    const int wm = warp >> 2, wn = warp & 3;
    const int g = lane >> 2, t = lane & 3;

#pragma unroll
    for (int mt = 0; mt < 4; mt++) {
#pragma unroll
        for (int mi = 0; mi < 2; mi++) {
            int m  = row0 + wm*64 + mt*16 + g + mi*8;
            int q  = m & 255, st = m >> 8;
            float lse = g_lse[m];
            float* orow = out + ((size_t)q * NSTEP + st) * VVn;
#pragma unroll
            for (int nt = 0; nt < 4; nt++) {
                int n = n0 + wn*32 + nt*8 + (t << 1);
                if (n < VVn) {
                    float* c = acc[mt][nt];
                    *(float2*)(orow + n) = make_float2(c[mi*2]   + logitb[n]   - lse,
                                                       c[mi*2+1] + logitb[n+1] - lse);
                }
            }
        }
    }
}

// ------------------------- preamble: all weight transposes -------------------------
__global__ __launch_bounds__(256)
void prep_transposes(const float* __restrict__ lw,
                     const float* __restrict__ wih, const float* __restrict__ whh,
                     const float* __restrict__ offw, const float* __restrict__ aww,
                     const float* __restrict__ hsw)
{
    __shared__ float s_t[64][65];
    const int blk = blockIdx.x;
    const int tx = threadIdx.x & 63, ty = threadIdx.x >> 6;

    if (blk < 632) {                                    // logitwt: 158 x 4
        const int n0 = (blk % 158) * 64, k0 = (blk / 158) * 64;
#pragma unroll
        for (int rr = ty; rr < 64; rr += 4)
            s_t[rr][tx] = (n0 + tx < VVn) ? lw[(size_t)(k0 + rr) * VVn + n0 + tx] : 0.f;
        __syncthreads();
#pragma unroll
        for (int rr = ty; rr < 64; rr += 4)
            g_logitwt[(size_t)(n0 + rr) * 256 + k0 + tx] = __float2bfloat16(s_t[tx][rr]);
    } else if (blk < 760) {                             // w21t: 16 n x 8 k tiles
        const int idx = blk - 632;
        const int n0 = (idx & 15) * 64, k0 = (idx >> 4) * 64;
#pragma unroll
        for (int rr = ty; rr < 64; rr += 4) {
            int k = k0 + rr, n = n0 + tx;
            int j = (n & 3) * 256 + (n >> 2);
            s_t[rr][tx] = (k < 256) ? wih[(size_t)(256 + k) * 1024 + j]
                                    : wih[(size_t)(k - 256) * 1024 + j];
        }
        __syncthreads();
#pragma unroll
        for (int rr = ty; rr < 64; rr += 4)
            g_w21t[(size_t)(n0 + rr) * 512 + k0 + tx] = __float2bfloat16(s_t[tx][rr]);
    } else if (blk < 856) {                             // bigw2t: 24 n x 4 k tiles
        const int idx = blk - 760;
        const int n0 = (idx % 24) * 64, k0 = (idx / 24) * 64;
#pragma unroll
        for (int rr = ty; rr < 64; rr += 4) {
            int k = k0 + rr, n = n0 + tx;
            float v;
            if (n < 128)      v = offw[k*128 + n];
            else if (n < 256) v = aww[k*128 + (n - 128)];
            else if (n < 512) v = hsw[k*256 + (n - 256)];
            else {
                int m = n - 512;
                v = whh[(size_t)k * 1024 + (m & 3) * 256 + (m >> 2)];
            }
            s_t[rr][tx] = v;
        }
        __syncthreads();
#pragma unroll
        for (int rr = ty; rr < 64; rr += 4)
            g_bigw2t[(size_t)(n0 + rr) * 256 + k0 + tx] = __float2bfloat16(s_t[tx][rr]);
    } else {                                            // wct: 20 n x 4 k tiles
        const int idx = blk - 856;
        const int n0 = (idx % 20) * 64, k0 = (idx / 20) * 64;
#pragma unroll
        for (int rr = ty; rr < 64; rr += 4) {
            int k = k0 + rr, n = n0 + tx;
            float v;
            if (n < 1024)
                v = wih[(size_t)(512 + k) * 1024 + (n & 3) * 256 + (n >> 2)];
            else {
                int m = n - 1024;
                v = (m < 128) ? offw[(256 + k)*128 + m] : aww[(256 + k)*128 + (m - 128)];
            }
            s_t[rr][tx] = v;
        }
        __syncthreads();
#pragma unroll
        for (int rr = ty; rr < 64; rr += 4)
            g_wct[(size_t)(n0 + rr) * 256 + k0 + tx] = __float2bfloat16(s_t[tx][rr]);
    }
}

__global__ __launch_bounds__(256)
void build_small(const float* __restrict__ ctxw, const float* __restrict__ valuew,
                 const float* __restrict__ hsb,  const float* __restrict__ ctxb,
                 const int*   __restrict__ seq,  const float* __restrict__ embw)
{
    const int blk = blockIdx.x, tid = threadIdx.x;
    if (blk < 256) {
        int q = blk;
        g_h[q*256 + tid] = 0.f;
        if (q == 0) g_hsbc[tid] = hsb[tid] + ctxb[tid];
    } else if (blk < 512) {
        int i = (blk - 256) * 256 + tid;
        if (i < 256*32) {
            int n = i >> 5, k = i & 31;
            g_ctxwt[n*32 + k] = __float2bfloat16(ctxw[k*256 + n]);
        }
        int n = i >> 8, k = i & 255;
        g_valuewt[n*256 + k] = __float2bfloat16(valuew[k*256 + n]);
    } else {
        // emb sequence precompute: 5120 blocks, one (step,query) row each
        int idx = blk - 512;
        int st = idx >> 8, q = idx & 255;
        int tok = (st == 0) ? 1 : seq[q*SSq + st - 1];
        g_embseq[((size_t)st*NEq + q)*256 + tid] = embw[(size_t)tok*256 + tid];
    }
}

// ------------------------- fused MSDA (warp-local; 1 block sync) -------------
__device__ __forceinline__ void msda_one(int n, const float rpn, const float* __restrict__ vr,
                                         float qoff, float qaw, float ab, char* smem)
{
    uint32_t* s_hsampb = (uint32_t*)smem;              // [128][17]
    float* s_hb  = (float*)(smem + 8704);
    float* s_off = (float*)(smem + 9728);
    float* s_aw  = (float*)(smem + 10240);
    const uint32_t* s_ctx  = (const uint32_t*)(smem + CTXOFF);
    const float*    s_aww  = (const float*)(smem + AWOFF);
    const float*    s_offb = (const float*)(smem + OBOFF);
    const float*    s_awb  = (const float*)(smem + ABOFF);
    const float*    s_hsbc = (const float*)(smem + HBOFF);

    const int b    = n >> 5;
    const int tid  = threadIdx.x;
    const int lane = tid & 31;
    const int w    = tid >> 5;

    // ---- phase A (block-wide) ----
    {
        float s = 0.f;
#pragma unroll
        for (int zu = 0; zu < 4; zu++)
            s += g_U[((size_t)zu*NEq + n)*1536 + 256 + tid];
        s_hb[tid] = s + s_hsbc[tid];
    }
    if (tid < 128) {
        float so = 0.f, sa = 0.f;
#pragma unroll
        for (int zu = 0; zu < 4; zu++) {
            so += g_U[((size_t)zu*NEq + n)*1536 + tid];
            sa += g_U[((size_t)zu*NEq + n)*1536 + 128 + tid];
        }
        so += qoff + s_offb[tid];
        sa += qaw  + s_awb[tid];
        s_off[tid] = so;
        float m = sa;
#pragma unroll
        for (int o = 8; o; o >>= 1) m = fmaxf(m, __shfl_xor_sync(0xffffffffu, m, o));
        float e = __expf(sa - m);
        float sm = e;
#pragma unroll
        for (int o = 8; o; o >>= 1) sm += __shfl_xor_sync(0xffffffffu, sm, o);
        s_aw[tid] = e / sm;
    }
    __syncthreads();

    // ---- phase B: sampling (warp-local rows w*16..w*16+15 = head w) ----
    {
        __nv_bfloat16* hs = (__nv_bfloat16*)s_hsampb;
#pragma unroll
        for (int i = 0; i < 16; i++) {
            int r = (w << 4) + i;
            int l = (r >> 2) & 3;
            int shape_l = 1024 >> l;
            int start_l = 2048 - (2048 >> l);
            float refl = rpn * vr[b*4 + l];
            float x = refl * (float)shape_l + s_off[r] - 0.5f;
            float x0f = floorf(x);
            float wf = x - x0f;
            int x0 = (int)x0f;
            const float* vbase = g_value + (((size_t)(b*HHn + w))*TTn + start_l) * HDn;
            float g0 = (x0 >= 0     && x0     < shape_l) ? vbase[(size_t)x0     * HDn + lane] : 0.f;
            float g1 = (x0 + 1 >= 0 && x0 + 1 < shape_l) ? vbase[(size_t)(x0+1) * HDn + lane] : 0.f;
            hs[r*34 + lane] = __float2bfloat16((g0 * (1.f - wf) + g1 * wf) * s_aw[r]);
        }
    }
    __syncwarp();

    // ---- phase C: alpha preactivations via mma (warp-local) ----
    const int g = lane >> 2, t = lane & 3;
    const int r0 = w << 4;
    float w0, w1;
    {
        uint32_t a[2][4];
#pragma unroll
        for (int ks = 0; ks < 2; ks++) {
            const uint32_t* ap = s_hsampb + (r0 + g) * 17 + ks*8 + t;
            a[ks][0] = ap[0];
            a[ks][1] = ap[8 * 17];
            a[ks][2] = ap[4];
            a[ks][3] = ap[8 * 17 + 4];
        }
        float p0 = 0.f, p1 = 0.f;
#pragma unroll
        for (int nb = 0; nb < 256; nb += 8) {
            float c[4] = {0.f, 0.f, 0.f, 0.f};
#pragma unroll
            for (int ks = 0; ks < 2; ks++) {
                const uint32_t* bp = s_ctx + (nb + g) * 17 + ks*8 + t;
                uint32_t bf2[2] = { bp[0], bp[4] };
                mma16816(c, a[ks], bf2);
            }
            int col = nb + (t << 1);
            float hb0 = s_hb[col], hb1 = s_hb[col + 1];
            float aw0 = s_aww[col], aw1 = s_aww[col + 1];
            p0 = fmaf(tanha(c[0] + hb0), aw0, fmaf(tanha(c[1] + hb1), aw1, p0));
            p1 = fmaf(tanha(c[2] + hb0), aw0, fmaf(tanha(c[3] + hb1), aw1, p1));
        }
        p0 += __shfl_xor_sync(0xffffffffu, p0, 1);
        p0 += __shfl_xor_sync(0xffffffffu, p0, 2);
        p1 += __shfl_xor_sync(0xffffffffu, p1, 1);
        p1 += __shfl_xor_sync(0xffffffffu, p1, 2);

        // ---- phase D: softmax over 16 rows (warp shuffles over g) ----
        float a0 = p0 + ab, a1 = p1 + ab;
        float m = fmaxf(a0, a1);
#pragma unroll
        for (int o = 4; o <= 16; o <<= 1) m = fmaxf(m, __shfl_xor_sync(0xffffffffu, m, o));
        float e0 = __expf(a0 - m), e1 = __expf(a1 - m);
        float s2 = e0 + e1;
#pragma unroll
        for (int o = 4; o <= 16; o <<= 1) s2 += __shfl_xor_sync(0xffffffffu, s2, o);
        float inv = 1.f / s2;
        w0 = e0 * inv;   // weight for row r0+g
        w1 = e1 * inv;   // weight for row r0+g+8
    }

    // ---- phase E: attn_res (warp-local; lane = hd) ----
    {
        const __nv_bfloat16* hs = (const __nv_bfloat16*)s_hsampb;
        float res = 0.f;
#pragma unroll
        for (int lp = 0; lp < 8; lp++) {
            float wv = __shfl_sync(0xffffffffu, w0, lp << 2);
            res = fmaf(wv, __bfloat162float(hs[(r0 + lp)*34 + lane]), res);
        }
#pragma unroll
        for (int lp = 0; lp < 8; lp++) {
            float wv = __shfl_sync(0xffffffffu, w1, lp << 2);
            res = fmaf(wv, __bfloat162float(hs[(r0 + 8 + lp)*34 + lane]), res);
        }
        g_ae[n*256 + (w << 5) + lane] = res;
    }
}

// ------------------------- persistent recurrent loop -------------------------
__global__ __launch_bounds__(256, 2)
void loop_kernel(const float* __restrict__ rp,   const float* __restrict__ vr,
                 const float* __restrict__ offb, const float* __restrict__ awb,
                 const float* __restrict__ alphaw, const float* __restrict__ alphab)
{
    extern __shared__ char smem[];
    const int blk   = blockIdx.x;
    const int grp   = blk >> 6;
    const int local = blk & 63;
    const int qbase = grp << 6;
    const int q     = qbase + local;     // this block's query
    const int tid   = threadIdx.x;
    unsigned bgen = g_ggen[grp*32];

    // persistent smem: ctx, alphaw, offb, awb, hsbc
    {
        uint32_t* s_ctx = (uint32_t*)(smem + CTXOFF);
        const uint32_t* cg = (const uint32_t*)g_ctxwt;
        for (int i = tid; i < 256*16; i += 256)
            s_ctx[(i >> 4)*17 + (i & 15)] = cg[i];
        ((float*)(smem + AWOFF))[tid] = alphaw[tid];
        if (tid < 128) {
            ((float*)(smem + OBOFF))[tid] = offb[tid];
            ((float*)(smem + ABOFF))[tid] = awb[tid];
        }
        ((float*)(smem + HBOFF))[tid] = g_hsbc[tid];
    }
    // per-block constants in registers
    const float rpn = rp[q];
    const float ab  = alphab[0];
    const float qoff = g_qgpc[q*1280 + 1024 + (tid & 127)];
    const float qaw  = g_qgpc[q*1280 + 1152 + (tid & 127)];
    const float4 qgate = *(const float4*)&g_qgpc[q*1280 + tid*4];
    float creg = 0.f;                   // LSTM cell state lives in registers

    for (int it = 0; it <= NSTEP; it++) {
        if (it > 0) {
            // ---- P0: LSTM (one query per block) ----
            {
                int d = tid;
                float4 s = make_float4(0.f, 0.f, 0.f, 0.f);
#pragma unroll
                for (int z = 0; z < 8; z++) {
                    float4 gp = *(const float4*)&g_gatesp[((size_t)z*NEq + q)*1024 + d*4];
                    s.x += gp.x; s.y += gp.y; s.z += gp.z; s.w += gp.w;
                }
#pragma unroll
                for (int zu = 0; zu < 4; zu++) {
                    float4 uv = *(const float4*)&g_U[((size_t)zu*NEq + q)*1536 + 512 + d*4];
                    s.x += uv.x; s.y += uv.y; s.z += uv.z; s.w += uv.w;
                }
                float gi = s.x + qgate.x, gf = s.y + qgate.y;
                float gg = s.z + qgate.z, go = s.w + qgate.w;
                float si = 1.f / (1.f + expf(-gi));
                float sf = 1.f / (1.f + expf(-gf));
                float so = 1.f / (1.f + expf(-go));
                float c2 = sf * creg + si * tanhf(gg);
                float h2 = so * tanhf(c2);
                creg = c2;
                g_h[q*256 + d] = h2;
                g_hseqb[((size_t)(it-1)*NEq + q)*DDim + d] = __float2bfloat16(h2);
            }
            if (it == NSTEP) break;
            groupbar(grp, ++bgen);
        }

        // ---- P1: U_g = h_g @ bigw2t (64x1536, K=256) split-K4 -> 48 blocks, 1-shot ----
        if (local < 48) {
            int bz = local / 12, bx = local % 12;
            float acc[2][4][4];
            gemm1shot(g_h + qbase*256 + bz*64, 256, g_bigw2t, 256, bx*128, bz*64, smem, acc);
            epi_partials(acc, g_U + (size_t)bz*NEq*1536 + (size_t)qbase*1536, 1536, bx*128, 0);
        }
        groupbar(grp, ++bgen);

        // ---- P2: MSDA, 1 query per block ----
        msda_one(q, rpn, vr, qoff, qaw, ab, smem);
        groupbar(grp, ++bgen);

        // ---- P3: gates_part split-K8: bz<4 attn, bz>=4 emb(precomputed) ----
        {
            int bz = local >> 3, bx = local & 7;
            const float* Ap;
            int kw;
            if (bz < 4) {
                Ap = g_ae + qbase*256 + bz*64;
                kw = bz*64;
            } else {
                Ap = g_embseq + ((size_t)it*NEq + qbase)*256 + (bz - 4)*64;
                kw = 256 + (bz - 4)*64;
            }
            float acc[2][4][4];
            gemm1shot(Ap, 256, g_w21t, 512, bx*128, kw, smem, acc);
            epi_partials(acc, g_gatesp + (size_t)bz*NEq*1024 + (size_t)qbase*1024, 1024, bx*128, 0);
        }
        groupbar(grp, ++bgen);
    }
}

// ------------------------- launch -------------------------
extern "C" void kernel_launch(void* const* d_in, const int* in_sizes, int n_in,
                              void* d_out, int out_size)
{
    const int*   seq    = (const int*)  d_in[0];
    const float* query  = (const float*)d_in[1];
    const float* rp     = (const float*)d_in[2];
    const float* enc    = (const float*)d_in[3];
    const float* mask   = (const float*)d_in[4];
    const float* vrr    = (const float*)d_in[5];
    const float* embw   = (const float*)d_in[6];
    const float* logitw = (const float*)d_in[7];
    const float* logitb = (const float*)d_in[8];
    const float* valuew = (const float*)d_in[9];
    const float* valueb = (const float*)d_in[10];
    const float* offw   = (const float*)d_in[11];
    const float* offb   = (const float*)d_in[12];
    const float* aww    = (const float*)d_in[13];
    const float* awb    = (const float*)d_in[14];
    const float* ctxw   = (const float*)d_in[15];
    const float* ctxb   = (const float*)d_in[16];
    const float* hsw    = (const float*)d_in[17];
    const float* hsb    = (const float*)d_in[18];
    const float* alphaw = (const float*)d_in[19];
    const float* alphab = (const float*)d_in[20];
    const float* wih    = (const float*)d_in[21];
    const float* whh    = (const float*)d_in[22];
    float* out = (float*)d_out;

    cudaFuncSetAttribute(gemms_pre,      cudaFuncAttributeMaxDynamicSharedMemorySize, SMEMSZ);
    cudaFuncSetAttribute(loop_kernel,    cudaFuncAttributeMaxDynamicSharedMemorySize, SMEMLOOP);
    cudaFuncSetAttribute(logits_stream1, cudaFuncAttributeMaxDynamicSharedMemorySize, SMEMS2);
    cudaFuncSetAttribute(logits_stream2, cudaFuncAttributeMaxDynamicSharedMemorySize, SMEMS2);

    // idx 0..2 preamble; idx 3 = loop_kernel (ncu displays idx 3)
    prep_transposes<<<936, 256>>>(logitw, wih, whh, offw, aww, hsw);
    build_small    <<<5632, 256>>>(ctxw, valuew, hsb, ctxb, seq, embw);
    gemms_pre      <<<520, 256, SMEMSZ>>>(enc, valueb, mask, query);

    loop_kernel<<<LOOPBLK, 256, SMEMLOOP>>>(rp, vrr, offb, awb, alphaw, alphab);

    logits_stream1<<<dim3(79, 40), 256, SMEMS2>>>(logitb);
    lse_reduce    <<<MTOT/8, 256>>>();
    logits_stream2<<<dim3(79, 40), 256, SMEMS2>>>(logitb, out);
}

// round 14
// speedup vs baseline: 1.4335x; 1.0799x over previous
#include <cuda_runtime.h>
#include <cuda_bf16.h>
#include <math.h>
#include <stdint.h>

#define NB    8
#define NEq   256
#define SSq   21
#define NSTEP 20
#define DDim  256
#define HHn   8
#define HDn   32
#define VVn   10000
#define TTn   1920
#define VPAD  10112
#define MTOT  (NSTEP*NEq)   // 5120
#define LOOPBLK 256
#define NWORK 40
#define TOTBLK (LOOPBLK + NWORK)   // 296 = exactly 2/SM x 148
#define NTASK (NSTEP*158)          // 3160
#define NGRP  4
#define GBLK  64
#define BST   12
#define SMEMSZ  (33792 + 2*128*BST*4)   // 46080 (preamble GEMM scratch)
#define CTXOFF  46080
#define AWOFF   (CTXOFF + 17408)        // 63488
#define OBOFF   (AWOFF + 1024)          // 64512
#define ABOFF   (OBOFF + 512)           // 65024
#define HBOFF   (ABOFF + 512)           // 65536
#define SMEMLOOP (HBOFF + 1024)         // 66560
#define SMEMS2  (2*128*12*4*2)          // 24576

// ------------------------- device scratch -------------------------
__device__ __align__(16) float g_value [NB*HHn*TTn*HDn];
__device__ __align__(16) float g_U     [4*NEq*1536];
__device__ __align__(16) float g_gatesp[8*NEq*1024];
__device__ __align__(16) float g_ae    [NEq*256];
__device__ __align__(16) float g_embseq[MTOT*256];
__device__ __align__(16) float g_qgpc  [NEq*1280];
__device__ __align__(16) float g_h     [NEq*DDim];
__device__ __align__(16) float g_hsbc  [256];
__device__ __align__(16) float g_lss   [MTOT*80];
__device__ __align__(16) float g_lse   [MTOT];
__device__ __align__(16) __nv_bfloat16 g_hseqb  [MTOT*DDim];
__device__ __align__(16) __nv_bfloat16 g_bigw2t [1536*256];
__device__ __align__(16) __nv_bfloat16 g_w21t   [1024*512];
__device__ __align__(16) __nv_bfloat16 g_wct    [1280*256];
__device__ __align__(16) __nv_bfloat16 g_logitwt[VPAD*256];
__device__ __align__(16) __nv_bfloat16 g_ctxwt  [256*32];
__device__ __align__(16) __nv_bfloat16 g_valuewt[256*256];

// barrier + work-stealing state
__device__ unsigned g_gcnt[NGRP*32];
__device__ volatile unsigned g_ggen[NGRP*32];
__device__ unsigned g_genbase[NGRP];
__device__ unsigned g_task;

// ------------------------- helpers -------------------------
__device__ __forceinline__ float tanha(float x) {
    float y; asm("tanh.approx.f32 %0, %1;" : "=f"(y) : "f"(x)); return y;
}
__device__ __forceinline__ void mma16816(float* c, const uint32_t* a, const uint32_t* b) {
    asm volatile(
        "mma.sync.aligned.m16n8k16.row.col.f32.bf16.bf16.f32 "
        "{%0,%1,%2,%3}, {%4,%5,%6,%7}, {%8,%9}, {%0,%1,%2,%3};"
        : "+f"(c[0]), "+f"(c[1]), "+f"(c[2]), "+f"(c[3])
        : "r"(a[0]), "r"(a[1]), "r"(a[2]), "r"(a[3]), "r"(b[0]), "r"(b[1]));
}
__device__ __forceinline__ void cpasync16(uint32_t dst, const void* src) {
    asm volatile("cp.async.cg.shared.global [%0], [%1], 16;" :: "r"(dst), "l"(src));
}

__device__ __forceinline__ void groupbar(int grp, unsigned gen) {
    __syncthreads();
    if (threadIdx.x == 0) {
        __threadfence();
        if (atomicAdd(&g_gcnt[grp*32], 1u) == (unsigned)(GBLK - 1)) {
            g_gcnt[grp*32] = 0;
            __threadfence();
            g_ggen[grp*32] = gen;
        } else {
            while ((int)(g_ggen[grp*32] - gen) < 0) { }
            __threadfence();
        }
    }
    __syncthreads();
}

// ------------------------- single-shot GEMM core (64x128 tile, K=64) -------------
__device__ __forceinline__ void gemm1shot(
    const float* __restrict__ A, int lda,
    const __nv_bfloat16* __restrict__ Wt, int ldw,
    int n0, int kbegW, char* smem, float acc[2][4][4])
{
    uint32_t* Asw = (uint32_t*)smem;            // [64][36] words
    uint32_t* Bsw = (uint32_t*)(smem + 9216);   // [128][36] words
    const int tid = threadIdx.x;
    const int lane = tid & 31, warp = tid >> 5;
    const int wm = warp >> 2, wn = warp & 3;
    const int g = lane >> 2, t = lane & 3;

    {
        const int br = tid >> 1;
        const int bo = (tid & 1) << 4;
        const uint32_t bsm = (uint32_t)__cvta_generic_to_shared(Bsw);
        const __nv_bfloat16* src = Wt + (size_t)(n0 + br) * ldw + kbegW + (bo << 1);
#pragma unroll
        for (int j = 0; j < 4; j++)
            cpasync16(bsm + (uint32_t)((br*36 + bo + j*4)*4), src + j*8);
        asm volatile("cp.async.commit_group;");
    }
    {
        const int ar = tid >> 2;
        const int ac = (tid & 3) << 4;
        const float* ap = A + (size_t)ar * lda + ac;
        uint32_t* dst = Asw + ar*36 + (ac >> 1);
#pragma unroll
        for (int j = 0; j < 4; j++) {
            float4 v = *(const float4*)(ap + j*4);
            __nv_bfloat162 p0 = __float22bfloat162_rn(make_float2(v.x, v.y));
            __nv_bfloat162 p1 = __float22bfloat162_rn(make_float2(v.z, v.w));
            dst[j*2]     = *(uint32_t*)&p0;
            dst[j*2 + 1] = *(uint32_t*)&p1;
        }
    }
    asm volatile("cp.async.wait_group 0;");
    __syncthreads();

#pragma unroll
    for (int i = 0; i < 2; i++)
#pragma unroll
        for (int j = 0; j < 4; j++)
#pragma unroll
            for (int q = 0; q < 4; q++) acc[i][j][q] = 0.f;

#pragma unroll
    for (int ks = 0; ks < 4; ks++) {
        const int wo = ks * 8;
        uint32_t a[2][4];
#pragma unroll
        for (int mt = 0; mt < 2; mt++) {
            const uint32_t* ap = Asw + (wm*32 + mt*16 + g) * 36 + wo + t;
            a[mt][0] = ap[0];
            a[mt][1] = ap[8 * 36];
            a[mt][2] = ap[4];
            a[mt][3] = ap[8 * 36 + 4];
        }
        uint32_t bf[4][2];
#pragma unroll
        for (int nt = 0; nt < 4; nt++) {
            const uint32_t* bp = Bsw + (wn*32 + nt*8 + g) * 36 + wo + t;
            bf[nt][0] = bp[0];
            bf[nt][1] = bp[4];
        }
#pragma unroll
        for (int mt = 0; mt < 2; mt++)
#pragma unroll
            for (int nt = 0; nt < 4; nt++)
                mma16816(acc[mt][nt], a[mt], bf[nt]);
    }
}

__device__ __forceinline__ void epi_partials(float acc[2][4][4], float* C, int N,
                                             int n0, int row0)
{
    const int lane = threadIdx.x & 31, warp = threadIdx.x >> 5;
    const int wm = warp >> 2, wn = warp & 3;
    const int g = lane >> 2, t = lane & 3;
#pragma unroll
    for (int mt = 0; mt < 2; mt++) {
        int m = row0 + wm*32 + mt*16 + g;
#pragma unroll
        for (int nt = 0; nt < 4; nt++) {
            int n = n0 + wn*32 + nt*8 + (t << 1);
            float* c = acc[mt][nt];
            *(float2*)(C + (size_t)m * N + n)       = make_float2(c[0], c[1]);
            *(float2*)(C + (size_t)(m + 8) * N + n) = make_float2(c[2], c[3]);
        }
    }
}

// ------------------------- multi-chunk GEMM core (preamble only) -------------------------
template<int KCHUNK>
__device__ __forceinline__ void gemm_core(
    const float* __restrict__ A, int lda,
    const __nv_bfloat16* __restrict__ Wt, int ldw,
    int n0, int row0, int kbeg, char* smem, float acc[2][4][4])
{
    uint32_t* Asw = (uint32_t*)smem;
    uint32_t* Bsw = (uint32_t*)(smem + 33792);
    const int SAW = 132;
    const int NKT = KCHUNK >> 4;
    constexpr int KC = (KCHUNK < 256) ? KCHUNK : 256;

    const int tid  = threadIdx.x;
    const int lane = tid & 31, warp = tid >> 5;
    const int wm = warp >> 2, wn = warp & 3;
    const int g = lane >> 2, t = lane & 3;
    const int bn = tid >> 1, bq = (tid & 1) << 3;
    const uint32_t bsm = (uint32_t)__cvta_generic_to_shared(Bsw);

    cpasync16(bsm + (uint32_t)((bn*BST + (bq>>1))*4),
              Wt + (size_t)(n0 + bn) * ldw + kbeg + bq);
    asm volatile("cp.async.commit_group;");

#pragma unroll
    for (int i = 0; i < 2; i++)
#pragma unroll
        for (int j = 0; j < 4; j++)
#pragma unroll
            for (int q = 0; q < 4; q++) acc[i][j][q] = 0.f;

#pragma unroll 1
    for (int ksg = 0; ksg < NKT; ksg++) {
        __syncthreads();
        if ((ksg & 15) == 0) {
            int kA = kbeg + ((ksg >> 4) << 8);
#pragma unroll
            for (int idx = tid * 4; idx < 64 * KC; idx += 1024) {
                int r = idx / KC, cc = idx % KC;
                float4 v = *(const float4*)(A + (size_t)(row0 + r) * lda + kA + cc);
                __nv_bfloat162 p0 = __float22bfloat162_rn(make_float2(v.x, v.y));
                __nv_bfloat162 p1 = __float22bfloat162_rn(make_float2(v.z, v.w));
                Asw[r * SAW + (cc >> 1)]     = *(uint32_t*)&p0;
                Asw[r * SAW + (cc >> 1) + 1] = *(uint32_t*)&p1;
            }
        }
        if (ksg + 1 < NKT)
            cpasync16(bsm + (uint32_t)(((((ksg+1)&1)*128*BST) + bn*BST + (bq>>1))*4),
                      Wt + (size_t)(n0 + bn) * ldw + kbeg + (ksg + 1) * 16 + bq);
        asm volatile("cp.async.commit_group;");
        asm volatile("cp.async.wait_group 1;");
        __syncthreads();

        const int wo = (ksg & 15) * 8;
        uint32_t a[2][4];
#pragma unroll
        for (int mt = 0; mt < 2; mt++) {
            const uint32_t* ap = Asw + (wm*32 + mt*16 + g) * SAW + wo + t;
            a[mt][0] = ap[0];
            a[mt][1] = ap[8 * SAW];
            a[mt][2] = ap[4];
            a[mt][3] = ap[8 * SAW + 4];
        }
        const uint32_t* bbase = Bsw + (ksg & 1) * 128 * BST;
        uint32_t bf[4][2];
#pragma unroll
        for (int nt = 0; nt < 4; nt++) {
            const uint32_t* bp = bbase + (wn*32 + nt*8 + g) * BST + t;
            bf[nt][0] = bp[0];
            bf[nt][1] = bp[4];
        }
#pragma unroll
        for (int mt = 0; mt < 2; mt++)
#pragma unroll
            for (int nt = 0; nt < 4; nt++)
                mma16816(acc[mt][nt], a[mt], bf[nt]);
    }
}

// ------------------------- fused preamble GEMMs -------------
__global__ __launch_bounds__(256, 2)
void gemms_pre(const float* __restrict__ enc, const float* __restrict__ valueb,
               const float* __restrict__ mask, const float* __restrict__ query)
{
    extern __shared__ char smem[];
    float acc[2][4][4];
    const int blk = blockIdx.x;
    if (blk < 480) {
        const int bx = blk & 1, by = blk >> 1;
        const int n0 = bx*128, row0 = by*64;
        gemm_core<256>(enc, 256, g_valuewt, 256, n0, row0, 0, smem, acc);
        const int lane = threadIdx.x & 31, warp = threadIdx.x >> 5;
        const int wm = warp >> 2, wn = warp & 3;
        const int g = lane >> 2, t = lane & 3;
#pragma unroll
        for (int mt = 0; mt < 2; mt++) {
#pragma unroll
            for (int mi = 0; mi < 2; mi++) {
                int m  = row0 + wm*32 + mt*16 + g + mi*8;
                int b  = m / TTn;
                int tt = m - b * TTn;
                float mk = mask[m];
#pragma unroll
                for (int nt = 0; nt < 4; nt++) {
                    int n = n0 + wn*32 + nt*8 + (t << 1);
                    int h = n >> 5, hd = n & 31;
                    float* c = acc[mt][nt];
                    float v0 = (c[mi*2]   + valueb[n])     * mk;
                    float v1 = (c[mi*2+1] + valueb[n + 1]) * mk;
                    *(float2*)(g_value + (((size_t)(b*HHn + h))*TTn + tt)*HDn + hd)
                        = make_float2(v0, v1);
                }
            }
        }
    } else {
        const int cb = blk - 480;
        const int bx = cb % 10, by = cb / 10;
        gemm_core<256>(query, 256, g_wct, 256, bx*128, by*64, 0, smem, acc);
        epi_partials(acc, g_qgpc + (size_t)(by*64)*1280, 1280, bx*128, 0);
    }
}

// ------------------------- streaming 128x128 GEMM core -------------------------
__device__ __forceinline__ void stream_core(const __nv_bfloat16* __restrict__ Ag0,
                                            const __nv_bfloat16* __restrict__ Bg0,
                                            char* smem, float acc[4][4][4])
{
    uint32_t* As = (uint32_t*)smem;
    uint32_t* Bs = (uint32_t*)(smem + 12288);
    const int tid = threadIdx.x;
    const int lane = tid & 31, warp = tid >> 5;
    const int wm = warp >> 2, wn = warp & 3;
    const int g = lane >> 2, t = lane & 3;
    const int lr = tid >> 1, lc = (tid & 1) << 3;
    const uint32_t asmb = (uint32_t)__cvta_generic_to_shared(As);
    const uint32_t bsmb = (uint32_t)__cvta_generic_to_shared(Bs);
    const uint32_t loff = (uint32_t)((lr*12 + (lc>>1))*4);
    const __nv_bfloat16* Ag = Ag0 + (size_t)lr*256 + lc;
    const __nv_bfloat16* Bg = Bg0 + (size_t)lr*256 + lc;

    cpasync16(asmb + loff, Ag);
    cpasync16(bsmb + loff, Bg);
    asm volatile("cp.async.commit_group;");

#pragma unroll
    for (int i = 0; i < 4; i++)
#pragma unroll
        for (int j = 0; j < 4; j++)
#pragma unroll
            for (int q = 0; q < 4; q++) acc[i][j][q] = 0.f;

#pragma unroll 1
    for (int ks = 0; ks < 16; ks++) {
        __syncthreads();
        if (ks + 1 < 16) {
            uint32_t bo = (uint32_t)(((ks + 1) & 1) * 6144);
            cpasync16(asmb + bo + loff, Ag + (ks + 1) * 16);
            cpasync16(bsmb + bo + loff, Bg + (ks + 1) * 16);
        }
        asm volatile("cp.async.commit_group;");
        asm volatile("cp.async.wait_group 1;");
        __syncthreads();

        const uint32_t* Ab = As + (ks & 1) * 1536;
        const uint32_t* Bb = Bs + (ks & 1) * 1536;
        uint32_t a[4][4];
#pragma unroll
        for (int mt = 0; mt < 4; mt++) {
            const uint32_t* ap = Ab + (wm*64 + mt*16 + g) * 12 + t;
            a[mt][0] = ap[0];
            a[mt][1] = ap[8 * 12];
            a[mt][2] = ap[4];
            a[mt][3] = ap[8 * 12 + 4];
        }
        uint32_t b[4][2];
#pragma unroll
        for (int nt = 0; nt < 4; nt++) {
            const uint32_t* bp = Bb + (wn*32 + nt*8 + g) * 12 + t;
            b[nt][0] = bp[0];
            b[nt][1] = bp[4];
        }
#pragma unroll
        for (int mt = 0; mt < 4; mt++)
#pragma unroll
            for (int nt = 0; nt < 4; nt++)
                mma16816(acc[mt][nt], a[mt], b[nt]);
    }
}

// pass-1 tile: sumexp partials for rows [row0,row0+128), cols [n0,n0+128)
__device__ void stream1_tile(int ntile, int row0, const float* __restrict__ logitb, char* smem)
{
    const int n0 = ntile * 128;
    float acc[4][4][4];
    stream_core(g_hseqb + (size_t)row0*256, g_logitwt + (size_t)n0*256, smem, acc);

    const int tid = threadIdx.x;
    const int lane = tid & 31, warp = tid >> 5;
    const int wm = warp >> 2, wn = warp & 3;
    const int g = lane >> 2, t = lane & 3;

    float bias_r[4][2];
#pragma unroll
    for (int nt = 0; nt < 4; nt++) {
        int n = n0 + wn*32 + nt*8 + (t << 1);
        bias_r[nt][0] = (n     < VVn) ? logitb[n]     : 0.f;
        bias_r[nt][1] = (n + 1 < VVn) ? logitb[n + 1] : 0.f;
    }

    __syncthreads();
    float* s_ps = (float*)smem;
#pragma unroll
    for (int mt = 0; mt < 4; mt++) {
#pragma unroll
        for (int mi = 0; mi < 2; mi++) {
            int mloc = wm*64 + mt*16 + g + mi*8;
            float ls = 0.f;
#pragma unroll
            for (int nt = 0; nt < 4; nt++) {
                int n = n0 + wn*32 + nt*8 + (t << 1);
#pragma unroll
                for (int e = 0; e < 2; e++)
                    if (n + e < VVn)
                        ls += __expf(acc[mt][nt][mi*2 + e] + bias_r[nt][e]);
            }
            ls += __shfl_xor_sync(0xffffffffu, ls, 1);
            ls += __shfl_xor_sync(0xffffffffu, ls, 2);
            if (t == 0) s_ps[mloc*4 + wn] = ls;
        }
    }
    __syncthreads();
    if (tid < 128) {
        float ls = s_ps[tid*4] + s_ps[tid*4+1] + s_ps[tid*4+2] + s_ps[tid*4+3];
        g_lss[(size_t)(row0 + tid)*80 + ntile] = ls;
    }
}

// work-stealing pool for pass-1 tiles (step-gated)
__device__ void worker_loop(const float* __restrict__ logitb, char* smem)
{
    int* s_tau = (int*)(smem + AWOFF);
    const int tid = threadIdx.x;
    for (;;) {
        __syncthreads();
        if (tid == 0) *s_tau = (int)atomicAdd(&g_task, 1u);
        __syncthreads();
        int tau = *s_tau;
        if (tau >= NTASK) return;
        int step = tau / 158;
        int r = tau - step * 158;
        int ntile = r >> 1, rh = r & 1;
        if (tid == 0) {
            int ga = rh * 2;
            unsigned need = 4u * (unsigned)(step + 1);
            while ((unsigned)(g_ggen[ga*32]     - g_genbase[ga])     < need) { }
            while ((unsigned)(g_ggen[(ga+1)*32] - g_genbase[ga+1])   < need) { }
        }
        __syncthreads();
        stream1_tile(ntile, step * 256 + rh * 128, logitb, smem);
    }
}

__global__ __launch_bounds__(256)
void lse_reduce()
{
    const int w = threadIdx.x >> 5, lane = threadIdx.x & 31;
    const int m = blockIdx.x * 8 + w;
    float s = 0.f;
    const float* p = g_lss + (size_t)m * 80;
    if (lane < 79)       s  = p[lane];
    if (lane + 32 < 79)  s += p[lane + 32];
    if (lane + 64 < 79)  s += p[lane + 64];
#pragma unroll
    for (int o = 16; o; o >>= 1) s += __shfl_xor_sync(0xffffffffu, s, o);
    if (lane == 0) g_lse[m] = logf(s);
}

__global__ __launch_bounds__(256, 2)
void logits_stream2(const float* __restrict__ logitb, float* __restrict__ out)
{
    extern __shared__ char smem[];
    float acc[4][4][4];
    const int n0 = blockIdx.x * 128, row0 = blockIdx.y * 128;
    stream_core(g_hseqb + (size_t)row0*256, g_logitwt + (size_t)n0*256, smem, acc);

    const int lane = threadIdx.x & 31, warp = threadIdx.x >> 5;
    const int wm = warp >> 2, wn = warp & 3;
    const int g = lane >> 2, t = lane & 3;

#pragma unroll
    for (int mt = 0; mt < 4; mt++) {
#pragma unroll
        for (int mi = 0; mi < 2; mi++) {
            int m  = row0 + wm*64 + mt*16 + g + mi*8;
            int q  = m & 255, st = m >> 8;
            float lse = g_lse[m];
            float* orow = out + ((size_t)q * NSTEP + st) * VVn;
#pragma unroll
            for (int nt = 0; nt < 4; nt++) {
                int n = n0 + wn*32 + nt*8 + (t << 1);
                if (n < VVn) {
                    float* c = acc[mt][nt];
                    *(float2*)(orow + n) = make_float2(c[mi*2]   + logitb[n]   - lse,
                                                       c[mi*2+1] + logitb[n+1] - lse);
                }
            }
        }
    }
}

// ------------------------- preamble: all weight transposes -------------------------
__global__ __launch_bounds__(256)
void prep_transposes(const float* __restrict__ lw,
                     const float* __restrict__ wih, const float* __restrict__ whh,
                     const float* __restrict__ offw, const float* __restrict__ aww,
                     const float* __restrict__ hsw)
{
    __shared__ float s_t[64][65];
    const int blk = blockIdx.x;
    const int tx = threadIdx.x & 63, ty = threadIdx.x >> 6;

    if (blk < 632) {
        const int n0 = (blk % 158) * 64, k0 = (blk / 158) * 64;
#pragma unroll
        for (int rr = ty; rr < 64; rr += 4)
            s_t[rr][tx] = (n0 + tx < VVn) ? lw[(size_t)(k0 + rr) * VVn + n0 + tx] : 0.f;
        __syncthreads();
#pragma unroll
        for (int rr = ty; rr < 64; rr += 4)
            g_logitwt[(size_t)(n0 + rr) * 256 + k0 + tx] = __float2bfloat16(s_t[tx][rr]);
    } else if (blk < 760) {
        const int idx = blk - 632;
        const int n0 = (idx & 15) * 64, k0 = (idx >> 4) * 64;
#pragma unroll
        for (int rr = ty; rr < 64; rr += 4) {
            int k = k0 + rr, n = n0 + tx;
            int j = (n & 3) * 256 + (n >> 2);
            s_t[rr][tx] = (k < 256) ? wih[(size_t)(256 + k) * 1024 + j]
                                    : wih[(size_t)(k - 256) * 1024 + j];
        }
        __syncthreads();
#pragma unroll
        for (int rr = ty; rr < 64; rr += 4)
            g_w21t[(size_t)(n0 + rr) * 512 + k0 + tx] = __float2bfloat16(s_t[tx][rr]);
    } else if (blk < 856) {
        const int idx = blk - 760;
        const int n0 = (idx % 24) * 64, k0 = (idx / 24) * 64;
#pragma unroll
        for (int rr = ty; rr < 64; rr += 4) {
            int k = k0 + rr, n = n0 + tx;
            float v;
            if (n < 128)      v = offw[k*128 + n];
            else if (n < 256) v = aww[k*128 + (n - 128)];
            else if (n < 512) v = hsw[k*256 + (n - 256)];
            else {
                int m = n - 512;
                v = whh[(size_t)k * 1024 + (m & 3) * 256 + (m >> 2)];
            }
            s_t[rr][tx] = v;
        }
        __syncthreads();
#pragma unroll
        for (int rr = ty; rr < 64; rr += 4)
            g_bigw2t[(size_t)(n0 + rr) * 256 + k0 + tx] = __float2bfloat16(s_t[tx][rr]);
    } else {
        const int idx = blk - 856;
        const int n0 = (idx % 20) * 64, k0 = (idx / 20) * 64;
#pragma unroll
        for (int rr = ty; rr < 64; rr += 4) {
            int k = k0 + rr, n = n0 + tx;
            float v;
            if (n < 1024)
                v = wih[(size_t)(512 + k) * 1024 + (n & 3) * 256 + (n >> 2)];
            else {
                int m = n - 1024;
                v = (m < 128) ? offw[(256 + k)*128 + m] : aww[(256 + k)*128 + (m - 128)];
            }
            s_t[rr][tx] = v;
        }
        __syncthreads();
#pragma unroll
        for (int rr = ty; rr < 64; rr += 4)
            g_wct[(size_t)(n0 + rr) * 256 + k0 + tx] = __float2bfloat16(s_t[tx][rr]);
    }
}

__global__ __launch_bounds__(256)
void build_small(const float* __restrict__ ctxw, const float* __restrict__ valuew,
                 const float* __restrict__ hsb,  const float* __restrict__ ctxb,
                 const int*   __restrict__ seq,  const float* __restrict__ embw)
{
    const int blk = blockIdx.x, tid = threadIdx.x;
    if (blk < 256) {
        int q = blk;
        g_h[q*256 + tid] = 0.f;
        if (q == 0) {
            g_hsbc[tid] = hsb[tid] + ctxb[tid];
            if (tid < NGRP) g_genbase[tid] = g_ggen[tid*32];   // snapshot gens
            if (tid == 0) g_task = 0;                          // reset task queue
        }
    } else if (blk < 512) {
        int i = (blk - 256) * 256 + tid;
        if (i < 256*32) {
            int n = i >> 5, k = i & 31;
            g_ctxwt[n*32 + k] = __float2bfloat16(ctxw[k*256 + n]);
        }
        int n = i >> 8, k = i & 255;
        g_valuewt[n*256 + k] = __float2bfloat16(valuew[k*256 + n]);
    } else {
        int idx = blk - 512;
        int st = idx >> 8, q = idx & 255;
        int tok = (st == 0) ? 1 : seq[q*SSq + st - 1];
        g_embseq[((size_t)st*NEq + q)*256 + tid] = embw[(size_t)tok*256 + tid];
    }
}

// ------------------------- fused MSDA (warp-local) -------------
__device__ __forceinline__ void msda_one(int n, const float rpn, const float* __restrict__ vr,
                                         float qoff, float qaw, float ab, char* smem)
{
    uint32_t* s_hsampb = (uint32_t*)smem;
    float* s_hb  = (float*)(smem + 8704);
    float* s_off = (float*)(smem + 9728);
    float* s_aw  = (float*)(smem + 10240);
    const uint32_t* s_ctx  = (const uint32_t*)(smem + CTXOFF);
    const float*    s_aww  = (const float*)(smem + AWOFF);
    const float*    s_offb = (const float*)(smem + OBOFF);
    const float*    s_awb  = (const float*)(smem + ABOFF);
    const float*    s_hsbc = (const float*)(smem + HBOFF);

    const int b    = n >> 5;
    const int tid  = threadIdx.x;
    const int lane = tid & 31;
    const int w    = tid >> 5;

    {
        float s = 0.f;
#pragma unroll
        for (int zu = 0; zu < 4; zu++)
            s += g_U[((size_t)zu*NEq + n)*1536 + 256 + tid];
        s_hb[tid] = s + s_hsbc[tid];
    }
    if (tid < 128) {
        float so = 0.f, sa = 0.f;
#pragma unroll
        for (int zu = 0; zu < 4; zu++) {
            so += g_U[((size_t)zu*NEq + n)*1536 + tid];
            sa += g_U[((size_t)zu*NEq + n)*1536 + 128 + tid];
        }
        so += qoff + s_offb[tid];
        sa += qaw  + s_awb[tid];
        s_off[tid] = so;
        float m = sa;
#pragma unroll
        for (int o = 8; o; o >>= 1) m = fmaxf(m, __shfl_xor_sync(0xffffffffu, m, o));
        float e = __expf(sa - m);
        float sm = e;
#pragma unroll
        for (int o = 8; o; o >>= 1) sm += __shfl_xor_sync(0xffffffffu, sm, o);
        s_aw[tid] = e / sm;
    }
    __syncthreads();

    {
        __nv_bfloat16* hs = (__nv_bfloat16*)s_hsampb;
#pragma unroll
        for (int i = 0; i < 16; i++) {
            int r = (w << 4) + i;
            int l = (r >> 2) & 3;
            int shape_l = 1024 >> l;
            int start_l = 2048 - (2048 >> l);
            float refl = rpn * vr[b*4 + l];
            float x = refl * (float)shape_l + s_off[r] - 0.5f;
            float x0f = floorf(x);
            float wf = x - x0f;
            int x0 = (int)x0f;
            const float* vbase = g_value + (((size_t)(b*HHn + w))*TTn + start_l) * HDn;
            float g0 = (x0 >= 0     && x0     < shape_l) ? vbase[(size_t)x0     * HDn + lane] : 0.f;
            float g1 = (x0 + 1 >= 0 && x0 + 1 < shape_l) ? vbase[(size_t)(x0+1) * HDn + lane] : 0.f;
            hs[r*34 + lane] = __float2bfloat16((g0 * (1.f - wf) + g1 * wf) * s_aw[r]);
        }
    }
    __syncwarp();

    const int g = lane >> 2, t = lane & 3;
    const int r0 = w << 4;
    float w0, w1;
    {
        uint32_t a[2][4];
#pragma unroll
        for (int ks = 0; ks < 2; ks++) {
            const uint32_t* ap = s_hsampb + (r0 + g) * 17 + ks*8 + t;
            a[ks][0] = ap[0];
            a[ks][1] = ap[8 * 17];
            a[ks][2] = ap[4];
            a[ks][3] = ap[8 * 17 + 4];
        }
        float p0 = 0.f, p1 = 0.f;
#pragma unroll
        for (int nb = 0; nb < 256; nb += 8) {
            float c[4] = {0.f, 0.f, 0.f, 0.f};
#pragma unroll
            for (int ks = 0; ks < 2; ks++) {
                const uint32_t* bp = s_ctx + (nb + g) * 17 + ks*8 + t;
                uint32_t bf2[2] = { bp[0], bp[4] };
                mma16816(c, a[ks], bf2);
            }
            int col = nb + (t << 1);
            float hb0 = s_hb[col], hb1 = s_hb[col + 1];
            float aw0 = s_aww[col], aw1 = s_aww[col + 1];
            p0 = fmaf(tanha(c[0] + hb0), aw0, fmaf(tanha(c[1] + hb1), aw1, p0));
            p1 = fmaf(tanha(c[2] + hb0), aw0, fmaf(tanha(c[3] + hb1), aw1, p1));
        }
        p0 += __shfl_xor_sync(0xffffffffu, p0, 1);
        p0 += __shfl_xor_sync(0xffffffffu, p0, 2);
        p1 += __shfl_xor_sync(0xffffffffu, p1, 1);
        p1 += __shfl_xor_sync(0xffffffffu, p1, 2);

        float a0 = p0 + ab, a1 = p1 + ab;
        float m = fmaxf(a0, a1);
#pragma unroll
        for (int o = 4; o <= 16; o <<= 1) m = fmaxf(m, __shfl_xor_sync(0xffffffffu, m, o));
        float e0 = __expf(a0 - m), e1 = __expf(a1 - m);
        float s2 = e0 + e1;
#pragma unroll
        for (int o = 4; o <= 16; o <<= 1) s2 += __shfl_xor_sync(0xffffffffu, s2, o);
        float inv = 1.f / s2;
        w0 = e0 * inv;
        w1 = e1 * inv;
    }

    {
        const __nv_bfloat16* hs = (const __nv_bfloat16*)s_hsampb;
        float res = 0.f;
#pragma unroll
        for (int lp = 0; lp < 8; lp++) {
            float wv = __shfl_sync(0xffffffffu, w0, lp << 2);
            res = fmaf(wv, __bfloat162float(hs[(r0 + lp)*34 + lane]), res);
        }
#pragma unroll
        for (int lp = 0; lp < 8; lp++) {
            float wv = __shfl_sync(0xffffffffu, w1, lp << 2);
            res = fmaf(wv, __bfloat162float(hs[(r0 + 8 + lp)*34 + lane]), res);
        }
        g_ae[n*256 + (w << 5) + lane] = res;
    }
}

// ------------------------- persistent loop + overlapped logits pass-1 -------------------
__global__ __launch_bounds__(256, 2)
void loop_kernel(const float* __restrict__ rp,   const float* __restrict__ vr,
                 const float* __restrict__ offb, const float* __restrict__ awb,
                 const float* __restrict__ alphaw, const float* __restrict__ alphab,
                 const float* __restrict__ logitb)
{
    extern __shared__ char smem[];
    const int blk = blockIdx.x;
    const int tid = threadIdx.x;

    if (blk >= LOOPBLK) {           // dedicated logits workers
        worker_loop(logitb, smem);
        return;
    }

    const int grp   = blk >> 6;
    const int local = blk & 63;
    const int qbase = grp << 6;
    const int q     = qbase + local;
    unsigned bgen = g_ggen[grp*32];

    {
        uint32_t* s_ctx = (uint32_t*)(smem + CTXOFF);
        const uint32_t* cg = (const uint32_t*)g_ctxwt;
        for (int i = tid; i < 256*16; i += 256)
            s_ctx[(i >> 4)*17 + (i & 15)] = cg[i];
        ((float*)(smem + AWOFF))[tid] = alphaw[tid];
        if (tid < 128) {
            ((float*)(smem + OBOFF))[tid] = offb[tid];
            ((float*)(smem + ABOFF))[tid] = awb[tid];
        }
        ((float*)(smem + HBOFF))[tid] = g_hsbc[tid];
    }
    const float rpn = rp[q];
    const float ab  = alphab[0];
    const float qoff = g_qgpc[q*1280 + 1024 + (tid & 127)];
    const float qaw  = g_qgpc[q*1280 + 1152 + (tid & 127)];
    const float4 qgate = *(const float4*)&g_qgpc[q*1280 + tid*4];
    float creg = 0.f;

    for (int it = 0; it <= NSTEP; it++) {
        if (it > 0) {
            // ---- P0: LSTM ----
            {
                int d = tid;
                float4 s = make_float4(0.f, 0.f, 0.f, 0.f);
#pragma unroll
                for (int z = 0; z < 8; z++) {
                    float4 gp = *(const float4*)&g_gatesp[((size_t)z*NEq + q)*1024 + d*4];
                    s.x += gp.x; s.y += gp.y; s.z += gp.z; s.w += gp.w;
                }
#pragma unroll
                for (int zu = 0; zu < 4; zu++) {
                    float4 uv = *(const float4*)&g_U[((size_t)zu*NEq + q)*1536 + 512 + d*4];
                    s.x += uv.x; s.y += uv.y; s.z += uv.z; s.w += uv.w;
                }
                float gi = s.x + qgate.x, gf = s.y + qgate.y;
                float gg = s.z + qgate.z, go = s.w + qgate.w;
                float si = 1.f / (1.f + expf(-gi));
                float sf = 1.f / (1.f + expf(-gf));
                float so = 1.f / (1.f + expf(-go));
                float c2 = sf * creg + si * tanhf(gg);
                float h2 = so * tanhf(c2);
                creg = c2;
                g_h[q*256 + d] = h2;
                g_hseqb[((size_t)(it-1)*NEq + q)*DDim + d] = __float2bfloat16(h2);
            }
            groupbar(grp, ++bgen);     // releases step it-1 for logits workers
            if (it == NSTEP) break;
        }

        // ---- P1: U ----
        if (local < 48) {
            int bz = local / 12, bx = local % 12;
            float acc[2][4][4];
            gemm1shot(g_h + qbase*256 + bz*64, 256, g_bigw2t, 256, bx*128, bz*64, smem, acc);
            epi_partials(acc, g_U + (size_t)bz*NEq*1536 + (size_t)qbase*1536, 1536, bx*128, 0);
        }
        groupbar(grp, ++bgen);

        // ---- P2: MSDA ----
        msda_one(q, rpn, vr, qoff, qaw, ab, smem);
        groupbar(grp, ++bgen);

        // ---- P3: gates partials ----
        {
            int bz = local >> 3, bx = local & 7;
            const float* Ap;
            int kw;
            if (bz < 4) {
                Ap = g_ae + qbase*256 + bz*64;
                kw = bz*64;
            } else {
                Ap = g_embseq + ((size_t)it*NEq + qbase)*256 + (bz - 4)*64;
                kw = 256 + (bz - 4)*64;
            }
            float acc[2][4][4];
            gemm1shot(Ap, 256, g_w21t, 512, bx*128, kw, smem, acc);
            epi_partials(acc, g_gatesp + (size_t)bz*NEq*1024 + (size_t)qbase*1024, 1024, bx*128, 0);
        }
        groupbar(grp, ++bgen);
    }

    // loop done for this block -> join the logits worker pool
    worker_loop(logitb, smem);
}

// ------------------------- launch -------------------------
extern "C" void kernel_launch(void* const* d_in, const int* in_sizes, int n_in,
                              void* d_out, int out_size)
{
    const int*   seq    = (const int*)  d_in[0];
    const float* query  = (const float*)d_in[1];
    const float* rp     = (const float*)d_in[2];
    const float* enc    = (const float*)d_in[3];
    const float* mask   = (const float*)d_in[4];
    const float* vrr    = (const float*)d_in[5];
    const float* embw   = (const float*)d_in[6];
    const float* logitw = (const float*)d_in[7];
    const float* logitb = (const float*)d_in[8];
    const float* valuew = (const float*)d_in[9];
    const float* valueb = (const float*)d_in[10];
    const float* offw   = (const float*)d_in[11];
    const float* offb   = (const float*)d_in[12];
    const float* aww    = (const float*)d_in[13];
    const float* awb    = (const float*)d_in[14];
    const float* ctxw   = (const float*)d_in[15];
    const float* ctxb   = (const float*)d_in[16];
    const float* hsw    = (const float*)d_in[17];
    const float* hsb    = (const float*)d_in[18];
    const float* alphaw = (const float*)d_in[19];
    const float* alphab = (const float*)d_in[20];
    const float* wih    = (const float*)d_in[21];
    const float* whh    = (const float*)d_in[22];
    float* out = (float*)d_out;

    cudaFuncSetAttribute(gemms_pre,      cudaFuncAttributeMaxDynamicSharedMemorySize, SMEMSZ);
    cudaFuncSetAttribute(loop_kernel,    cudaFuncAttributeMaxDynamicSharedMemorySize, SMEMLOOP);
    cudaFuncSetAttribute(logits_stream2, cudaFuncAttributeMaxDynamicSharedMemorySize, SMEMS2);

    prep_transposes<<<936, 256>>>(logitw, wih, whh, offw, aww, hsw);
    build_small    <<<5632, 256>>>(ctxw, valuew, hsb, ctxb, seq, embw);
    gemms_pre      <<<520, 256, SMEMSZ>>>(enc, valueb, mask, query);

    // loop + overlapped logits pass-1 (work stealing), grid = exact residency
    loop_kernel<<<TOTBLK, 256, SMEMLOOP>>>(rp, vrr, offb, awb, alphaw, alphab, logitb);

    lse_reduce    <<<MTOT/8, 256>>>();
    logits_stream2<<<dim3(79, 40), 256, SMEMS2>>>(logitb, out);
}